// round 1
// baseline (speedup 1.0000x reference)
#include <cuda_runtime.h>

// Problem constants
constexpr int Bn  = 2;
constexpr int Ln  = 2048;
constexpr int Dn  = 1024;
constexpr int Hn  = 16;
constexpr int HDn = 64;
constexpr int NROW = Bn * Ln;   // 4096

// Scratch (device globals: allocation-free)
__device__ float g_qkv[(size_t)3 * Bn * Hn * Ln * HDn];  // [3][B][H][L][HD]
__device__ float g_y[(size_t)NROW * Dn];                 // [B*L][D], col = h*64+hd

// ---------------------------------------------------------------------------
// SGEMM 128x128x16, 256 threads, 8x8 per thread.
// QKV variant: A = x [4096,1024], B = Wq/Wk/Wv [1024,1024], C -> g_qkv in
// [B,H,L,HD] layout. blockIdx.z selects q/k/v.
// ---------------------------------------------------------------------------
__global__ void __launch_bounds__(256) proj_qkv_kernel(
    const float* __restrict__ x,
    const float* __restrict__ Wq,
    const float* __restrict__ Wk,
    const float* __restrict__ Wv)
{
    __shared__ float As[16][128];   // transposed A tile: As[k][m]
    __shared__ float Bs[16][128];   // Bs[k][n]

    const float* W = (blockIdx.z == 0) ? Wq : (blockIdx.z == 1) ? Wk : Wv;
    float* out = g_qkv + (size_t)blockIdx.z * ((size_t)Bn * Hn * Ln * HDn);

    const int tid  = threadIdx.x;
    const int tn   = tid & 15;
    const int tm   = tid >> 4;
    const int row0 = blockIdx.y * 128;
    const int col0 = blockIdx.x * 128;

    float acc[8][8];
    #pragma unroll
    for (int i = 0; i < 8; i++)
        #pragma unroll
        for (int j = 0; j < 8; j++) acc[i][j] = 0.f;

    for (int k0 = 0; k0 < Dn; k0 += 16) {
        #pragma unroll
        for (int it = 0; it < 2; it++) {
            int idx = tid + it * 256;          // 0..511
            int r = idx >> 2, c = idx & 3;
            float4 v = *(const float4*)(x + (size_t)(row0 + r) * Dn + k0 + c * 4);
            As[c*4+0][r] = v.x; As[c*4+1][r] = v.y;
            As[c*4+2][r] = v.z; As[c*4+3][r] = v.w;
        }
        #pragma unroll
        for (int it = 0; it < 2; it++) {
            int idx = tid + it * 256;
            int kk = idx >> 5, c = idx & 31;
            *(float4*)&Bs[kk][c*4] =
                *(const float4*)(W + (size_t)(k0 + kk) * Dn + col0 + c * 4);
        }
        __syncthreads();
        #pragma unroll
        for (int kk = 0; kk < 16; kk++) {
            float a[8], bv[8];
            *(float4*)&a[0]  = *(float4*)&As[kk][tm*4];
            *(float4*)&a[4]  = *(float4*)&As[kk][tm*4 + 64];
            *(float4*)&bv[0] = *(float4*)&Bs[kk][tn*4];
            *(float4*)&bv[4] = *(float4*)&Bs[kk][tn*4 + 64];
            #pragma unroll
            for (int i = 0; i < 8; i++)
                #pragma unroll
                for (int j = 0; j < 8; j++)
                    acc[i][j] = fmaf(a[i], bv[j], acc[i][j]);
        }
        __syncthreads();
    }

    // Epilogue: write into [B,H,L,HD] layout
    #pragma unroll
    for (int i = 0; i < 8; i++) {
        int r = row0 + tm*4 + (i & 3) + ((i >> 2) << 6);  // global row (b,l)
        int b = r >> 11;          // / 2048
        int lpos = r & 2047;
        #pragma unroll
        for (int j = 0; j < 8; j++) {
            int c = col0 + tn*4 + (j & 3) + ((j >> 2) << 6); // global col (h,hd)
            int h  = c >> 6;
            int hd = c & 63;
            out[(((size_t)(b * Hn + h) * Ln + lpos) << 6) + hd] = acc[i][j];
        }
    }
}

// ---------------------------------------------------------------------------
// Output projection: A = g_y [4096,1024], B = Wo [1024,1024], C = d_out
// ---------------------------------------------------------------------------
__global__ void __launch_bounds__(256) proj_out_kernel(
    const float* __restrict__ Wo,
    float* __restrict__ out)
{
    __shared__ float As[16][128];
    __shared__ float Bs[16][128];

    const int tid  = threadIdx.x;
    const int tn   = tid & 15;
    const int tm   = tid >> 4;
    const int row0 = blockIdx.y * 128;
    const int col0 = blockIdx.x * 128;

    float acc[8][8];
    #pragma unroll
    for (int i = 0; i < 8; i++)
        #pragma unroll
        for (int j = 0; j < 8; j++) acc[i][j] = 0.f;

    for (int k0 = 0; k0 < Dn; k0 += 16) {
        #pragma unroll
        for (int it = 0; it < 2; it++) {
            int idx = tid + it * 256;
            int r = idx >> 2, c = idx & 3;
            float4 v = *(const float4*)(g_y + (size_t)(row0 + r) * Dn + k0 + c * 4);
            As[c*4+0][r] = v.x; As[c*4+1][r] = v.y;
            As[c*4+2][r] = v.z; As[c*4+3][r] = v.w;
        }
        #pragma unroll
        for (int it = 0; it < 2; it++) {
            int idx = tid + it * 256;
            int kk = idx >> 5, c = idx & 31;
            *(float4*)&Bs[kk][c*4] =
                *(const float4*)(Wo + (size_t)(k0 + kk) * Dn + col0 + c * 4);
        }
        __syncthreads();
        #pragma unroll
        for (int kk = 0; kk < 16; kk++) {
            float a[8], bv[8];
            *(float4*)&a[0]  = *(float4*)&As[kk][tm*4];
            *(float4*)&a[4]  = *(float4*)&As[kk][tm*4 + 64];
            *(float4*)&bv[0] = *(float4*)&Bs[kk][tn*4];
            *(float4*)&bv[4] = *(float4*)&Bs[kk][tn*4 + 64];
            #pragma unroll
            for (int i = 0; i < 8; i++)
                #pragma unroll
                for (int j = 0; j < 8; j++)
                    acc[i][j] = fmaf(a[i], bv[j], acc[i][j]);
        }
        __syncthreads();
    }

    #pragma unroll
    for (int i = 0; i < 8; i++) {
        int r = row0 + tm*4 + (i & 3) + ((i >> 2) << 6);
        float4 o0 = make_float4(acc[i][0], acc[i][1], acc[i][2], acc[i][3]);
        float4 o1 = make_float4(acc[i][4], acc[i][5], acc[i][6], acc[i][7]);
        *(float4*)(out + (size_t)r * Dn + col0 + tn*4)      = o0;
        *(float4*)(out + (size_t)r * Dn + col0 + tn*4 + 64) = o1;
    }
}

// ---------------------------------------------------------------------------
// Flash attention, fp32. One CTA per (b, h, 64-query tile). 256 threads as
// 16x16; each thread owns a 4x4 block of S / O. Online softmax in registers;
// row-group reductions via 16-lane shuffles (lanes with same tm are a
// contiguous half-warp).
// ---------------------------------------------------------------------------
constexpr int ATTN_SMEM_FLOATS = 64*64 + 64*65 + 64*68 + 64*68;
constexpr int ATTN_SMEM_BYTES  = ATTN_SMEM_FLOATS * 4;   // 67,840 B

__global__ void __launch_bounds__(256) attn_kernel()
{
    extern __shared__ float sm[];
    float* Qs = sm;               // [64][64]
    float* Ks = Qs + 64*64;       // [64][65]  pad 1 -> 2-way max on reads
    float* Vs = Ks + 64*65;       // [64][68]  pad 4 keeps float4 alignment
    float* Ps = Vs + 64*68;       // [64][68]

    const int qt  = blockIdx.x;   // query tile 0..31
    const int h   = blockIdx.y;
    const int b   = blockIdx.z;
    const int tid = threadIdx.x;
    const int tn  = tid & 15;
    const int tm  = tid >> 4;

    const size_t plane = (size_t)Bn * Hn * Ln * HDn;
    const size_t base  = ((size_t)(b * Hn + h) * Ln) * HDn;
    const float* qg = g_qkv + base;
    const float* kg = g_qkv + plane + base;
    const float* vg = g_qkv + 2 * plane + base;

    // Load Q tile, pre-scaled by 1/sqrt(hd) = 0.125
    #pragma unroll
    for (int it = 0; it < 4; it++) {
        int idx = tid + it * 256;
        int r = idx >> 4, c = (idx & 15) * 4;
        float4 v = *(const float4*)(qg + (size_t)(qt*64 + r) * HDn + c);
        v.x *= 0.125f; v.y *= 0.125f; v.z *= 0.125f; v.w *= 0.125f;
        *(float4*)&Qs[r*64 + c] = v;
    }

    float m[4], l[4], O[4][4];
    #pragma unroll
    for (int i = 0; i < 4; i++) {
        m[i] = -1e30f; l[i] = 0.f;
        #pragma unroll
        for (int j = 0; j < 4; j++) O[i][j] = 0.f;
    }

    for (int kt = 0; kt <= qt; kt++) {
        __syncthreads();   // protect K/V/P reuse from previous iteration
        #pragma unroll
        for (int it = 0; it < 4; it++) {
            int idx = tid + it * 256;
            int r = idx >> 4, c = (idx & 15) * 4;
            float4 kv = *(const float4*)(kg + (size_t)(kt*64 + r) * HDn + c);
            Ks[r*65 + c + 0] = kv.x;
            Ks[r*65 + c + 1] = kv.y;
            Ks[r*65 + c + 2] = kv.z;
            Ks[r*65 + c + 3] = kv.w;
            float4 vv = *(const float4*)(vg + (size_t)(kt*64 + r) * HDn + c);
            *(float4*)&Vs[r*68 + c] = vv;
        }
        __syncthreads();

        // S = Q * K^T  (64x64, 4x4 per thread)
        float S[4][4];
        #pragma unroll
        for (int i = 0; i < 4; i++)
            #pragma unroll
            for (int j = 0; j < 4; j++) S[i][j] = 0.f;

        #pragma unroll 8
        for (int d = 0; d < 64; d++) {
            float a0 = Qs[(tm*4+0)*64 + d];
            float a1 = Qs[(tm*4+1)*64 + d];
            float a2 = Qs[(tm*4+2)*64 + d];
            float a3 = Qs[(tm*4+3)*64 + d];
            float b0 = Ks[(tn*4+0)*65 + d];
            float b1 = Ks[(tn*4+1)*65 + d];
            float b2 = Ks[(tn*4+2)*65 + d];
            float b3 = Ks[(tn*4+3)*65 + d];
            S[0][0] = fmaf(a0,b0,S[0][0]); S[0][1] = fmaf(a0,b1,S[0][1]);
            S[0][2] = fmaf(a0,b2,S[0][2]); S[0][3] = fmaf(a0,b3,S[0][3]);
            S[1][0] = fmaf(a1,b0,S[1][0]); S[1][1] = fmaf(a1,b1,S[1][1]);
            S[1][2] = fmaf(a1,b2,S[1][2]); S[1][3] = fmaf(a1,b3,S[1][3]);
            S[2][0] = fmaf(a2,b0,S[2][0]); S[2][1] = fmaf(a2,b1,S[2][1]);
            S[2][2] = fmaf(a2,b2,S[2][2]); S[2][3] = fmaf(a2,b3,S[2][3]);
            S[3][0] = fmaf(a3,b0,S[3][0]); S[3][1] = fmaf(a3,b1,S[3][1]);
            S[3][2] = fmaf(a3,b2,S[3][2]); S[3][3] = fmaf(a3,b3,S[3][3]);
        }

        // Causal mask (only the diagonal tile needs it)
        if (kt == qt) {
            #pragma unroll
            for (int i = 0; i < 4; i++)
                #pragma unroll
                for (int j = 0; j < 4; j++)
                    if (tn*4 + j > tm*4 + i) S[i][j] = -1e30f;
        }

        // Online softmax per row (row group = 16 lanes sharing tm)
        #pragma unroll
        for (int i = 0; i < 4; i++) {
            float rmax = fmaxf(fmaxf(S[i][0], S[i][1]), fmaxf(S[i][2], S[i][3]));
            #pragma unroll
            for (int off = 8; off > 0; off >>= 1)
                rmax = fmaxf(rmax, __shfl_xor_sync(0xffffffffu, rmax, off));
            float newm = fmaxf(m[i], rmax);
            float corr = __expf(m[i] - newm);
            float rsum = 0.f;
            #pragma unroll
            for (int j = 0; j < 4; j++) {
                S[i][j] = __expf(S[i][j] - newm);
                rsum += S[i][j];
            }
            #pragma unroll
            for (int off = 8; off > 0; off >>= 1)
                rsum += __shfl_xor_sync(0xffffffffu, rsum, off);
            m[i] = newm;
            l[i] = l[i] * corr + rsum;
            #pragma unroll
            for (int j = 0; j < 4; j++) O[i][j] *= corr;
            *(float4*)&Ps[(tm*4+i)*68 + tn*4] =
                make_float4(S[i][0], S[i][1], S[i][2], S[i][3]);
        }
        __syncthreads();

        // O += P * V  (thread owns rows tm*4+i, dims tn*4+j)
        #pragma unroll 8
        for (int kv = 0; kv < 64; kv++) {
            float4 v4 = *(float4*)&Vs[kv*68 + tn*4];
            #pragma unroll
            for (int i = 0; i < 4; i++) {
                float p = Ps[(tm*4+i)*68 + kv];
                O[i][0] = fmaf(p, v4.x, O[i][0]);
                O[i][1] = fmaf(p, v4.y, O[i][1]);
                O[i][2] = fmaf(p, v4.z, O[i][2]);
                O[i][3] = fmaf(p, v4.w, O[i][3]);
            }
        }
    }

    // Finalize: divide by l and write y in [B,L,H,HD] (= [4096,1024]) layout
    #pragma unroll
    for (int i = 0; i < 4; i++) {
        float inv = 1.f / l[i];
        int qrow = qt*64 + tm*4 + i;
        float4 o = make_float4(O[i][0]*inv, O[i][1]*inv, O[i][2]*inv, O[i][3]*inv);
        *(float4*)(g_y + (size_t)(b * Ln + qrow) * Dn + h*64 + tn*4) = o;
    }
}

// ---------------------------------------------------------------------------
extern "C" void kernel_launch(void* const* d_in, const int* in_sizes, int n_in,
                              void* d_out, int out_size)
{
    (void)in_sizes; (void)n_in; (void)out_size;
    const float* x  = (const float*)d_in[0];
    const float* Wq = (const float*)d_in[1];
    const float* Wk = (const float*)d_in[2];
    const float* Wv = (const float*)d_in[3];
    const float* Wo = (const float*)d_in[4];
    float* out = (float*)d_out;

    cudaFuncSetAttribute(attn_kernel,
                         cudaFuncAttributeMaxDynamicSharedMemorySize,
                         ATTN_SMEM_BYTES);

    proj_qkv_kernel<<<dim3(Dn/128, NROW/128, 3), 256>>>(x, Wq, Wk, Wv);
    attn_kernel<<<dim3(Ln/64, Hn, Bn), 256, ATTN_SMEM_BYTES>>>();
    proj_out_kernel<<<dim3(Dn/128, NROW/128, 1), 256>>>(Wo, out);
}

// round 3
// speedup vs baseline: 1.4617x; 1.4617x over previous
#include <cuda_runtime.h>
#include <cuda_bf16.h>
#include <cstdint>

// Problem constants
constexpr int Bn  = 2;
constexpr int Ln  = 2048;
constexpr int Dn  = 1024;
constexpr int Hn  = 16;
constexpr int HDn = 64;
constexpr int NROW = Bn * Ln;   // 4096

// Scratch (device globals: allocation-free)
__device__ float g_qkv[(size_t)3 * Bn * Hn * Ln * HDn];  // [3][B][H][L][HD]
__device__ float g_y[(size_t)NROW * Dn];                 // [B*L][D], col = h*64+hd

// ---------------------------------------------------------------------------
// Helpers
// ---------------------------------------------------------------------------
__device__ __forceinline__ uint32_t s2u(const void* p) {
    uint32_t a;
    asm("{ .reg .u64 t; cvta.to.shared.u64 t, %1; cvt.u32.u64 %0, t; }"
        : "=r"(a) : "l"(p));
    return a;
}

__device__ __forceinline__ void ldm_x4(uint32_t* r, uint32_t a) {
    asm volatile("ldmatrix.sync.aligned.m8n8.x4.shared.b16 {%0,%1,%2,%3}, [%4];"
                 : "=r"(r[0]), "=r"(r[1]), "=r"(r[2]), "=r"(r[3]) : "r"(a));
}
__device__ __forceinline__ void ldm_x2t(uint32_t* r, uint32_t a) {
    asm volatile("ldmatrix.sync.aligned.m8n8.x2.trans.shared.b16 {%0,%1}, [%2];"
                 : "=r"(r[0]), "=r"(r[1]) : "r"(a));
}
__device__ __forceinline__ void mma_bf16(float* c, const uint32_t* a,
                                         const uint32_t* b) {
    asm volatile(
        "mma.sync.aligned.m16n8k16.row.col.f32.bf16.bf16.f32 "
        "{%0,%1,%2,%3}, {%4,%5,%6,%7}, {%8,%9}, {%0,%1,%2,%3};"
        : "+f"(c[0]), "+f"(c[1]), "+f"(c[2]), "+f"(c[3])
        : "r"(a[0]), "r"(a[1]), "r"(a[2]), "r"(a[3]), "r"(b[0]), "r"(b[1]));
}

__device__ __forceinline__ uint16_t bfu(float f) {
    __nv_bfloat16 h = __float2bfloat16_rn(f);
    return *(uint16_t*)&h;
}
__device__ __forceinline__ float bff(uint16_t u) {
    __nv_bfloat16 h = *(__nv_bfloat16*)&u;
    return __bfloat162float(h);
}

// Split float4 into packed bf16 hi (uint2) and lo (uint2)
__device__ __forceinline__ void split4(float4 v, uint2& hi, uint2& lo) {
    uint16_t h0 = bfu(v.x), h1 = bfu(v.y), h2 = bfu(v.z), h3 = bfu(v.w);
    uint16_t l0 = bfu(v.x - bff(h0)), l1 = bfu(v.y - bff(h1));
    uint16_t l2 = bfu(v.z - bff(h2)), l3 = bfu(v.w - bff(h3));
    hi = make_uint2((uint32_t)h0 | ((uint32_t)h1 << 16),
                    (uint32_t)h2 | ((uint32_t)h3 << 16));
    lo = make_uint2((uint32_t)l0 | ((uint32_t)l1 << 16),
                    (uint32_t)l2 | ((uint32_t)l3 << 16));
}

// ---------------------------------------------------------------------------
// bf16-split GEMM via mma.sync: C[128x64 tile] = A[4096,1024] * W[1024,1024]
// 3 passes (hi*hi + hi*lo + lo*hi), fp32 accumulate in registers.
// mode 0: A = x, W in {Wq,Wk,Wv} by blockIdx.z, C -> g_qkv [B,H,L,HD]
// mode 1: A = g_y, W = W0, C -> outp row-major [4096,1024]
// ---------------------------------------------------------------------------
constexpr int A_STRIDE = 40;   // bf16 elems per row (32 data + 8 pad) = 80 B
constexpr int B_STRIDE = 72;   // bf16 elems per row (64 data + 8 pad) = 144 B

__global__ void __launch_bounds__(256) gemm_mma_kernel(
    const float* __restrict__ A,
    const float* __restrict__ W0,
    const float* __restrict__ W1,
    const float* __restrict__ W2,
    float* __restrict__ outp,
    int mode)
{
    __shared__ __align__(16) uint16_t Ah[128 * A_STRIDE];
    __shared__ __align__(16) uint16_t Al[128 * A_STRIDE];
    __shared__ __align__(16) uint16_t Bh[32 * B_STRIDE];
    __shared__ __align__(16) uint16_t Bl[32 * B_STRIDE];

    const int tid  = threadIdx.x;
    const int lane = tid & 31;
    const int w    = tid >> 5;
    const int wm   = w & 3;        // 4 warp rows of 32
    const int wn   = w >> 2;       // 2 warp cols of 32
    const int row0 = blockIdx.y * 128;
    const int col0 = blockIdx.x * 64;

    const float* Ap = (mode == 0) ? A : g_y;
    const float* W  = (blockIdx.z == 0) ? W0 : (blockIdx.z == 1) ? W1 : W2;

    float C[2][4][4];
    #pragma unroll
    for (int mi = 0; mi < 2; mi++)
        #pragma unroll
        for (int ni = 0; ni < 4; ni++)
            #pragma unroll
            for (int q = 0; q < 4; q++) C[mi][ni][q] = 0.f;

    // Prefetch stage 0 into registers
    float4 apf[4], bpf[2];
    #pragma unroll
    for (int i = 0; i < 4; i++) {
        int idx = tid + i * 256;
        int r = idx >> 3, c4 = idx & 7;
        apf[i] = *(const float4*)(Ap + (size_t)(row0 + r) * Dn + c4 * 4);
    }
    #pragma unroll
    for (int i = 0; i < 2; i++) {
        int idx = tid + i * 256;
        int r = idx >> 4, c4 = idx & 15;
        bpf[i] = *(const float4*)(W + (size_t)r * Dn + col0 + c4 * 4);
    }

    const uint32_t ah_s = s2u(Ah), al_s = s2u(Al);
    const uint32_t bh_s = s2u(Bh), bl_s = s2u(Bl);

    for (int c = 0; c < 32; c++) {
        // Store current stage (convert + split)
        #pragma unroll
        for (int i = 0; i < 4; i++) {
            int idx = tid + i * 256;
            int r = idx >> 3, c4 = idx & 7;
            uint2 hi, lo;
            split4(apf[i], hi, lo);
            *(uint2*)(Ah + r * A_STRIDE + c4 * 4) = hi;
            *(uint2*)(Al + r * A_STRIDE + c4 * 4) = lo;
        }
        #pragma unroll
        for (int i = 0; i < 2; i++) {
            int idx = tid + i * 256;
            int r = idx >> 4, c4 = idx & 15;
            uint2 hi, lo;
            split4(bpf[i], hi, lo);
            *(uint2*)(Bh + r * B_STRIDE + c4 * 4) = hi;
            *(uint2*)(Bl + r * B_STRIDE + c4 * 4) = lo;
        }
        __syncthreads();

        // Prefetch next stage (LDGs overlap the MMA work below)
        if (c < 31) {
            const int k0 = (c + 1) * 32;
            #pragma unroll
            for (int i = 0; i < 4; i++) {
                int idx = tid + i * 256;
                int r = idx >> 3, c4 = idx & 7;
                apf[i] = *(const float4*)(Ap + (size_t)(row0 + r) * Dn + k0 + c4 * 4);
            }
            #pragma unroll
            for (int i = 0; i < 2; i++) {
                int idx = tid + i * 256;
                int r = idx >> 4, c4 = idx & 15;
                bpf[i] = *(const float4*)(W + (size_t)(k0 + r) * Dn + col0 + c4 * 4);
            }
        }

        // Compute: 2 k16 steps x 3 passes
        #pragma unroll
        for (int ks = 0; ks < 2; ks++) {
            uint32_t ahf[2][4], alf[2][4], bhf[4][2], blf[4][2];
            #pragma unroll
            for (int mi = 0; mi < 2; mi++) {
                uint32_t off = (uint32_t)((wm * 32 + mi * 16 + (lane & 15)) * (A_STRIDE * 2)
                                          + ks * 32 + (lane >> 4) * 16);
                ldm_x4(ahf[mi], ah_s + off);
                ldm_x4(alf[mi], al_s + off);
            }
            #pragma unroll
            for (int ni = 0; ni < 4; ni++) {
                uint32_t off = (uint32_t)((ks * 16 + (lane & 15)) * (B_STRIDE * 2)
                                          + (wn * 32 + ni * 8) * 2);
                ldm_x2t(bhf[ni], bh_s + off);
                ldm_x2t(blf[ni], bl_s + off);
            }
            #pragma unroll
            for (int mi = 0; mi < 2; mi++)
                #pragma unroll
                for (int ni = 0; ni < 4; ni++) {
                    mma_bf16(C[mi][ni], ahf[mi], bhf[ni]);
                    mma_bf16(C[mi][ni], ahf[mi], blf[ni]);
                    mma_bf16(C[mi][ni], alf[mi], bhf[ni]);
                }
        }
        __syncthreads();
    }

    // Epilogue
    #pragma unroll
    for (int mi = 0; mi < 2; mi++)
        #pragma unroll
        for (int ni = 0; ni < 4; ni++) {
            int row = row0 + wm * 32 + mi * 16 + (lane >> 2);
            int col = col0 + wn * 32 + ni * 8 + (lane & 3) * 2;
            if (mode == 0) {
                float* outq = g_qkv + (size_t)blockIdx.z * ((size_t)Bn * Hn * Ln * HDn);
                int h = col >> 6, hd = col & 63;
                {
                    int b = row >> 11, l = row & 2047;
                    float* d = outq + (((size_t)(b * Hn + h) * Ln + l) << 6) + hd;
                    d[0] = C[mi][ni][0]; d[1] = C[mi][ni][1];
                }
                {
                    int r2 = row + 8;
                    int b = r2 >> 11, l = r2 & 2047;
                    float* d = outq + (((size_t)(b * Hn + h) * Ln + l) << 6) + hd;
                    d[0] = C[mi][ni][2]; d[1] = C[mi][ni][3];
                }
            } else {
                float* d0 = outp + (size_t)row * Dn + col;
                float* d1 = outp + (size_t)(row + 8) * Dn + col;
                d0[0] = C[mi][ni][0]; d0[1] = C[mi][ni][1];
                d1[0] = C[mi][ni][2]; d1[1] = C[mi][ni][3];
            }
        }
}

// ---------------------------------------------------------------------------
// Flash attention, fp32 (unchanged — round-4 target)
// ---------------------------------------------------------------------------
constexpr int ATTN_SMEM_FLOATS = 64*64 + 64*65 + 64*68 + 64*68;
constexpr int ATTN_SMEM_BYTES  = ATTN_SMEM_FLOATS * 4;   // 67,840 B

__global__ void __launch_bounds__(256) attn_kernel()
{
    extern __shared__ float smf[];
    float* Qs = smf;              // [64][64]
    float* Ks = Qs + 64*64;       // [64][65]
    float* Vs = Ks + 64*65;       // [64][68]
    float* Ps = Vs + 64*68;       // [64][68]

    const int qt  = blockIdx.x;
    const int h   = blockIdx.y;
    const int b   = blockIdx.z;
    const int tid = threadIdx.x;
    const int tn  = tid & 15;
    const int tm  = tid >> 4;

    const size_t plane = (size_t)Bn * Hn * Ln * HDn;
    const size_t base  = ((size_t)(b * Hn + h) * Ln) * HDn;
    const float* qg = g_qkv + base;
    const float* kg = g_qkv + plane + base;
    const float* vg = g_qkv + 2 * plane + base;

    #pragma unroll
    for (int it = 0; it < 4; it++) {
        int idx = tid + it * 256;
        int r = idx >> 4, c = (idx & 15) * 4;
        float4 v = *(const float4*)(qg + (size_t)(qt*64 + r) * HDn + c);
        v.x *= 0.125f; v.y *= 0.125f; v.z *= 0.125f; v.w *= 0.125f;
        *(float4*)&Qs[r*64 + c] = v;
    }

    float m[4], l[4], O[4][4];
    #pragma unroll
    for (int i = 0; i < 4; i++) {
        m[i] = -1e30f; l[i] = 0.f;
        #pragma unroll
        for (int j = 0; j < 4; j++) O[i][j] = 0.f;
    }

    for (int kt = 0; kt <= qt; kt++) {
        __syncthreads();
        #pragma unroll
        for (int it = 0; it < 4; it++) {
            int idx = tid + it * 256;
            int r = idx >> 4, c = (idx & 15) * 4;
            float4 kv = *(const float4*)(kg + (size_t)(kt*64 + r) * HDn + c);
            Ks[r*65 + c + 0] = kv.x;
            Ks[r*65 + c + 1] = kv.y;
            Ks[r*65 + c + 2] = kv.z;
            Ks[r*65 + c + 3] = kv.w;
            float4 vv = *(const float4*)(vg + (size_t)(kt*64 + r) * HDn + c);
            *(float4*)&Vs[r*68 + c] = vv;
        }
        __syncthreads();

        float S[4][4];
        #pragma unroll
        for (int i = 0; i < 4; i++)
            #pragma unroll
            for (int j = 0; j < 4; j++) S[i][j] = 0.f;

        #pragma unroll 8
        for (int d = 0; d < 64; d++) {
            float a0 = Qs[(tm*4+0)*64 + d];
            float a1 = Qs[(tm*4+1)*64 + d];
            float a2 = Qs[(tm*4+2)*64 + d];
            float a3 = Qs[(tm*4+3)*64 + d];
            float b0 = Ks[(tn*4+0)*65 + d];
            float b1 = Ks[(tn*4+1)*65 + d];
            float b2 = Ks[(tn*4+2)*65 + d];
            float b3 = Ks[(tn*4+3)*65 + d];
            S[0][0] = fmaf(a0,b0,S[0][0]); S[0][1] = fmaf(a0,b1,S[0][1]);
            S[0][2] = fmaf(a0,b2,S[0][2]); S[0][3] = fmaf(a0,b3,S[0][3]);
            S[1][0] = fmaf(a1,b0,S[1][0]); S[1][1] = fmaf(a1,b1,S[1][1]);
            S[1][2] = fmaf(a1,b2,S[1][2]); S[1][3] = fmaf(a1,b3,S[1][3]);
            S[2][0] = fmaf(a2,b0,S[2][0]); S[2][1] = fmaf(a2,b1,S[2][1]);
            S[2][2] = fmaf(a2,b2,S[2][2]); S[2][3] = fmaf(a2,b3,S[2][3]);
            S[3][0] = fmaf(a3,b0,S[3][0]); S[3][1] = fmaf(a3,b1,S[3][1]);
            S[3][2] = fmaf(a3,b2,S[3][2]); S[3][3] = fmaf(a3,b3,S[3][3]);
        }

        if (kt == qt) {
            #pragma unroll
            for (int i = 0; i < 4; i++)
                #pragma unroll
                for (int j = 0; j < 4; j++)
                    if (tn*4 + j > tm*4 + i) S[i][j] = -1e30f;
        }

        #pragma unroll
        for (int i = 0; i < 4; i++) {
            float rmax = fmaxf(fmaxf(S[i][0], S[i][1]), fmaxf(S[i][2], S[i][3]));
            #pragma unroll
            for (int off = 8; off > 0; off >>= 1)
                rmax = fmaxf(rmax, __shfl_xor_sync(0xffffffffu, rmax, off));
            float newm = fmaxf(m[i], rmax);
            float corr = __expf(m[i] - newm);
            float rsum = 0.f;
            #pragma unroll
            for (int j = 0; j < 4; j++) {
                S[i][j] = __expf(S[i][j] - newm);
                rsum += S[i][j];
            }
            #pragma unroll
            for (int off = 8; off > 0; off >>= 1)
                rsum += __shfl_xor_sync(0xffffffffu, rsum, off);
            m[i] = newm;
            l[i] = l[i] * corr + rsum;
            #pragma unroll
            for (int j = 0; j < 4; j++) O[i][j] *= corr;
            *(float4*)&Ps[(tm*4+i)*68 + tn*4] =
                make_float4(S[i][0], S[i][1], S[i][2], S[i][3]);
        }
        __syncthreads();

        #pragma unroll 8
        for (int kv = 0; kv < 64; kv++) {
            float4 v4 = *(float4*)&Vs[kv*68 + tn*4];
            #pragma unroll
            for (int i = 0; i < 4; i++) {
                float p = Ps[(tm*4+i)*68 + kv];
                O[i][0] = fmaf(p, v4.x, O[i][0]);
                O[i][1] = fmaf(p, v4.y, O[i][1]);
                O[i][2] = fmaf(p, v4.z, O[i][2]);
                O[i][3] = fmaf(p, v4.w, O[i][3]);
            }
        }
    }

    #pragma unroll
    for (int i = 0; i < 4; i++) {
        float inv = 1.f / l[i];
        int qrow = qt*64 + tm*4 + i;
        float4 o = make_float4(O[i][0]*inv, O[i][1]*inv, O[i][2]*inv, O[i][3]*inv);
        *(float4*)(g_y + (size_t)(b * Ln + qrow) * Dn + h*64 + tn*4) = o;
    }
}

// ---------------------------------------------------------------------------
extern "C" void kernel_launch(void* const* d_in, const int* in_sizes, int n_in,
                              void* d_out, int out_size)
{
    (void)in_sizes; (void)n_in; (void)out_size;
    const float* x  = (const float*)d_in[0];
    const float* Wq = (const float*)d_in[1];
    const float* Wk = (const float*)d_in[2];
    const float* Wv = (const float*)d_in[3];
    const float* Wo = (const float*)d_in[4];
    float* out = (float*)d_out;

    cudaFuncSetAttribute(attn_kernel,
                         cudaFuncAttributeMaxDynamicSharedMemorySize,
                         ATTN_SMEM_BYTES);

    gemm_mma_kernel<<<dim3(Dn/64, NROW/128, 3), 256>>>(
        x, Wq, Wk, Wv, nullptr, 0);
    attn_kernel<<<dim3(Ln/64, Hn, Bn), 256, ATTN_SMEM_BYTES>>>();
    gemm_mma_kernel<<<dim3(Dn/64, NROW/128, 1), 256>>>(
        nullptr, Wo, Wo, Wo, out, 1);
}

// round 4
// speedup vs baseline: 2.3749x; 1.6247x over previous
#include <cuda_runtime.h>
#include <cuda_bf16.h>
#include <cstdint>

// Problem constants
constexpr int Bn  = 2;
constexpr int Ln  = 2048;
constexpr int Dn  = 1024;
constexpr int Hn  = 16;
constexpr int HDn = 64;
constexpr int NROW = Bn * Ln;   // 4096

// Scratch (device globals: allocation-free)
__device__ float g_qkv[(size_t)3 * Bn * Hn * Ln * HDn];  // [3][B][H][L][HD]
__device__ float g_y[(size_t)NROW * Dn];                 // [B*L][D], col = h*64+hd

// ---------------------------------------------------------------------------
// Helpers
// ---------------------------------------------------------------------------
__device__ __forceinline__ uint32_t s2u(const void* p) {
    uint32_t a;
    asm("{ .reg .u64 t; cvta.to.shared.u64 t, %1; cvt.u32.u64 %0, t; }"
        : "=r"(a) : "l"(p));
    return a;
}

__device__ __forceinline__ void ldm_x4(uint32_t* r, uint32_t a) {
    asm volatile("ldmatrix.sync.aligned.m8n8.x4.shared.b16 {%0,%1,%2,%3}, [%4];"
                 : "=r"(r[0]), "=r"(r[1]), "=r"(r[2]), "=r"(r[3]) : "r"(a));
}
__device__ __forceinline__ void ldm_x4t(uint32_t* r, uint32_t a) {
    asm volatile("ldmatrix.sync.aligned.m8n8.x4.trans.shared.b16 {%0,%1,%2,%3}, [%4];"
                 : "=r"(r[0]), "=r"(r[1]), "=r"(r[2]), "=r"(r[3]) : "r"(a));
}
__device__ __forceinline__ void ldm_x2t(uint32_t* r, uint32_t a) {
    asm volatile("ldmatrix.sync.aligned.m8n8.x2.trans.shared.b16 {%0,%1}, [%2];"
                 : "=r"(r[0]), "=r"(r[1]) : "r"(a));
}
__device__ __forceinline__ void mma_bf16(float* c, const uint32_t* a,
                                         const uint32_t* b) {
    asm volatile(
        "mma.sync.aligned.m16n8k16.row.col.f32.bf16.bf16.f32 "
        "{%0,%1,%2,%3}, {%4,%5,%6,%7}, {%8,%9}, {%0,%1,%2,%3};"
        : "+f"(c[0]), "+f"(c[1]), "+f"(c[2]), "+f"(c[3])
        : "r"(a[0]), "r"(a[1]), "r"(a[2]), "r"(a[3]), "r"(b[0]), "r"(b[1]));
}

__device__ __forceinline__ uint16_t bfu(float f) {
    __nv_bfloat16 h = __float2bfloat16_rn(f);
    return *(uint16_t*)&h;
}
__device__ __forceinline__ float bff(uint16_t u) {
    __nv_bfloat16 h = *(__nv_bfloat16*)&u;
    return __bfloat162float(h);
}

// Split float4 into packed bf16 hi (uint2) and lo (uint2)
__device__ __forceinline__ void split4(float4 v, uint2& hi, uint2& lo) {
    uint16_t h0 = bfu(v.x), h1 = bfu(v.y), h2 = bfu(v.z), h3 = bfu(v.w);
    uint16_t l0 = bfu(v.x - bff(h0)), l1 = bfu(v.y - bff(h1));
    uint16_t l2 = bfu(v.z - bff(h2)), l3 = bfu(v.w - bff(h3));
    hi = make_uint2((uint32_t)h0 | ((uint32_t)h1 << 16),
                    (uint32_t)h2 | ((uint32_t)h3 << 16));
    lo = make_uint2((uint32_t)l0 | ((uint32_t)l1 << 16),
                    (uint32_t)l2 | ((uint32_t)l3 << 16));
}

// Pack two floats into bf16x2 hi and lo words
__device__ __forceinline__ void packhl(float f0, float f1,
                                       uint32_t& h2, uint32_t& l2) {
    uint16_t h0 = bfu(f0), h1 = bfu(f1);
    uint16_t l0 = bfu(f0 - bff(h0)), l1 = bfu(f1 - bff(h1));
    h2 = (uint32_t)h0 | ((uint32_t)h1 << 16);
    l2 = (uint32_t)l0 | ((uint32_t)l1 << 16);
}

// ---------------------------------------------------------------------------
// bf16-split GEMM via mma.sync (unchanged from round 3)
// ---------------------------------------------------------------------------
constexpr int A_STRIDE = 40;
constexpr int B_STRIDE = 72;

__global__ void __launch_bounds__(256) gemm_mma_kernel(
    const float* __restrict__ A,
    const float* __restrict__ W0,
    const float* __restrict__ W1,
    const float* __restrict__ W2,
    float* __restrict__ outp,
    int mode)
{
    __shared__ __align__(16) uint16_t Ah[128 * A_STRIDE];
    __shared__ __align__(16) uint16_t Al[128 * A_STRIDE];
    __shared__ __align__(16) uint16_t Bh[32 * B_STRIDE];
    __shared__ __align__(16) uint16_t Bl[32 * B_STRIDE];

    const int tid  = threadIdx.x;
    const int lane = tid & 31;
    const int w    = tid >> 5;
    const int wm   = w & 3;
    const int wn   = w >> 2;
    const int row0 = blockIdx.y * 128;
    const int col0 = blockIdx.x * 64;

    const float* Ap = (mode == 0) ? A : g_y;
    const float* W  = (blockIdx.z == 0) ? W0 : (blockIdx.z == 1) ? W1 : W2;

    float C[2][4][4];
    #pragma unroll
    for (int mi = 0; mi < 2; mi++)
        #pragma unroll
        for (int ni = 0; ni < 4; ni++)
            #pragma unroll
            for (int q = 0; q < 4; q++) C[mi][ni][q] = 0.f;

    float4 apf[4], bpf[2];
    #pragma unroll
    for (int i = 0; i < 4; i++) {
        int idx = tid + i * 256;
        int r = idx >> 3, c4 = idx & 7;
        apf[i] = *(const float4*)(Ap + (size_t)(row0 + r) * Dn + c4 * 4);
    }
    #pragma unroll
    for (int i = 0; i < 2; i++) {
        int idx = tid + i * 256;
        int r = idx >> 4, c4 = idx & 15;
        bpf[i] = *(const float4*)(W + (size_t)r * Dn + col0 + c4 * 4);
    }

    const uint32_t ah_s = s2u(Ah), al_s = s2u(Al);
    const uint32_t bh_s = s2u(Bh), bl_s = s2u(Bl);

    for (int c = 0; c < 32; c++) {
        #pragma unroll
        for (int i = 0; i < 4; i++) {
            int idx = tid + i * 256;
            int r = idx >> 3, c4 = idx & 7;
            uint2 hi, lo;
            split4(apf[i], hi, lo);
            *(uint2*)(Ah + r * A_STRIDE + c4 * 4) = hi;
            *(uint2*)(Al + r * A_STRIDE + c4 * 4) = lo;
        }
        #pragma unroll
        for (int i = 0; i < 2; i++) {
            int idx = tid + i * 256;
            int r = idx >> 4, c4 = idx & 15;
            uint2 hi, lo;
            split4(bpf[i], hi, lo);
            *(uint2*)(Bh + r * B_STRIDE + c4 * 4) = hi;
            *(uint2*)(Bl + r * B_STRIDE + c4 * 4) = lo;
        }
        __syncthreads();

        if (c < 31) {
            const int k0 = (c + 1) * 32;
            #pragma unroll
            for (int i = 0; i < 4; i++) {
                int idx = tid + i * 256;
                int r = idx >> 3, c4 = idx & 7;
                apf[i] = *(const float4*)(Ap + (size_t)(row0 + r) * Dn + k0 + c4 * 4);
            }
            #pragma unroll
            for (int i = 0; i < 2; i++) {
                int idx = tid + i * 256;
                int r = idx >> 4, c4 = idx & 15;
                bpf[i] = *(const float4*)(W + (size_t)(k0 + r) * Dn + col0 + c4 * 4);
            }
        }

        #pragma unroll
        for (int ks = 0; ks < 2; ks++) {
            uint32_t ahf[2][4], alf[2][4], bhf[4][2], blf[4][2];
            #pragma unroll
            for (int mi = 0; mi < 2; mi++) {
                uint32_t off = (uint32_t)((wm * 32 + mi * 16 + (lane & 15)) * (A_STRIDE * 2)
                                          + ks * 32 + (lane >> 4) * 16);
                ldm_x4(ahf[mi], ah_s + off);
                ldm_x4(alf[mi], al_s + off);
            }
            #pragma unroll
            for (int ni = 0; ni < 4; ni++) {
                uint32_t off = (uint32_t)((ks * 16 + (lane & 15)) * (B_STRIDE * 2)
                                          + (wn * 32 + ni * 8) * 2);
                ldm_x2t(bhf[ni], bh_s + off);
                ldm_x2t(blf[ni], bl_s + off);
            }
            #pragma unroll
            for (int mi = 0; mi < 2; mi++)
                #pragma unroll
                for (int ni = 0; ni < 4; ni++) {
                    mma_bf16(C[mi][ni], ahf[mi], bhf[ni]);
                    mma_bf16(C[mi][ni], ahf[mi], blf[ni]);
                    mma_bf16(C[mi][ni], alf[mi], bhf[ni]);
                }
        }
        __syncthreads();
    }

    #pragma unroll
    for (int mi = 0; mi < 2; mi++)
        #pragma unroll
        for (int ni = 0; ni < 4; ni++) {
            int row = row0 + wm * 32 + mi * 16 + (lane >> 2);
            int col = col0 + wn * 32 + ni * 8 + (lane & 3) * 2;
            if (mode == 0) {
                float* outq = g_qkv + (size_t)blockIdx.z * ((size_t)Bn * Hn * Ln * HDn);
                int h = col >> 6, hd = col & 63;
                {
                    int b = row >> 11, l = row & 2047;
                    float* d = outq + (((size_t)(b * Hn + h) * Ln + l) << 6) + hd;
                    d[0] = C[mi][ni][0]; d[1] = C[mi][ni][1];
                }
                {
                    int r2 = row + 8;
                    int b = r2 >> 11, l = r2 & 2047;
                    float* d = outq + (((size_t)(b * Hn + h) * Ln + l) << 6) + hd;
                    d[0] = C[mi][ni][2]; d[1] = C[mi][ni][3];
                }
            } else {
                float* d0 = outp + (size_t)row * Dn + col;
                float* d1 = outp + (size_t)(row + 8) * Dn + col;
                d0[0] = C[mi][ni][0]; d0[1] = C[mi][ni][1];
                d1[0] = C[mi][ni][2]; d1[1] = C[mi][ni][3];
            }
        }
}

// ---------------------------------------------------------------------------
// Tensor-core flash attention (bf16 hi/lo split, 3 passes for both GEMMs).
// CTA: 128 queries x one (b,h). 8 warps, each owns 16 query rows x full width.
// ---------------------------------------------------------------------------
constexpr int QS = 72;   // bf16 row stride for all attn smem tiles
// smem element offsets
constexpr int OFF_QH = 0;
constexpr int OFF_QL = 128 * QS;          // 9216
constexpr int OFF_KH = 2 * 128 * QS;      // 18432
constexpr int OFF_KL = OFF_KH + 64 * QS;  // 23040
constexpr int OFF_VH = OFF_KL + 64 * QS;  // 27648
constexpr int OFF_VL = OFF_VH + 64 * QS;  // 32256
constexpr int ATTN_SMEM_ELEMS = OFF_VL + 64 * QS;  // 36864
constexpr int ATTN_SMEM_BYTES = ATTN_SMEM_ELEMS * 2;  // 73728

__global__ void __launch_bounds__(256) attn_kernel()
{
    extern __shared__ uint16_t smh[];

    const int qt   = blockIdx.x;    // 128-query tile, 0..15
    const int h    = blockIdx.y;
    const int b    = blockIdx.z;
    const int tid  = threadIdx.x;
    const int lane = tid & 31;
    const int wid  = tid >> 5;
    const int r0   = wid * 16;      // warp's query-row base within tile

    const size_t plane = (size_t)Bn * Hn * Ln * HDn;
    const size_t base  = ((size_t)(b * Hn + h) * Ln) * HDn;
    const float* qg = g_qkv + base;
    const float* kg = g_qkv + plane + base;
    const float* vg = g_qkv + 2 * plane + base;

    const uint32_t sb = s2u(smh);

    // Load + scale + split Q tile [128][64]
    #pragma unroll
    for (int i = 0; i < 8; i++) {
        int idx = tid + i * 256;
        int r = idx >> 4, c4 = idx & 15;
        float4 v = *(const float4*)(qg + (size_t)(qt * 128 + r) * HDn + c4 * 4);
        v.x *= 0.125f; v.y *= 0.125f; v.z *= 0.125f; v.w *= 0.125f;
        uint2 hi, lo;
        split4(v, hi, lo);
        *(uint2*)(smh + OFF_QH + r * QS + c4 * 4) = hi;
        *(uint2*)(smh + OFF_QL + r * QS + c4 * 4) = lo;
    }

    float m0 = -1e30f, m1 = -1e30f, l0 = 0.f, l1 = 0.f;
    float O[8][4];
    #pragma unroll
    for (int nt = 0; nt < 8; nt++)
        #pragma unroll
        for (int q = 0; q < 4; q++) O[nt][q] = 0.f;

    const int qbase = qt * 128 + r0;
    const int ktmax = 2 * qt + 2;

    for (int kt = 0; kt < ktmax; kt++) {
        __syncthreads();
        // Load + split K,V tiles [64][64]
        #pragma unroll
        for (int i = 0; i < 4; i++) {
            int idx = tid + i * 256;
            int r = idx >> 4, c4 = idx & 15;
            const size_t goff = (size_t)(kt * 64 + r) * HDn + c4 * 4;
            uint2 hi, lo;
            split4(*(const float4*)(kg + goff), hi, lo);
            *(uint2*)(smh + OFF_KH + r * QS + c4 * 4) = hi;
            *(uint2*)(smh + OFF_KL + r * QS + c4 * 4) = lo;
            split4(*(const float4*)(vg + goff), hi, lo);
            *(uint2*)(smh + OFF_VH + r * QS + c4 * 4) = hi;
            *(uint2*)(smh + OFF_VL + r * QS + c4 * 4) = lo;
        }
        __syncthreads();

        // Skip fully-masked warp iterations (no syncs below)
        if (kt * 64 > qbase + 15) continue;

        // ---- S = Q * K^T (3-pass split) ----
        float S[8][4];
        #pragma unroll
        for (int nt = 0; nt < 8; nt++)
            #pragma unroll
            for (int q = 0; q < 4; q++) S[nt][q] = 0.f;

        #pragma unroll
        for (int ks = 0; ks < 4; ks++) {
            uint32_t qh[4], ql[4];
            uint32_t qaddr = sb + (uint32_t)(((r0 + (lane & 15)) * QS
                              + ks * 16 + ((lane >> 4) * 8)) * 2);
            ldm_x4(qh, qaddr + OFF_QH * 2);
            ldm_x4(ql, qaddr + OFF_QL * 2);
            #pragma unroll
            for (int ntp = 0; ntp < 4; ntp++) {
                uint32_t kaddr = sb + (uint32_t)(((ntp * 16 + (lane & 7)
                                  + ((lane >> 4) << 3)) * QS
                                  + ((lane >> 3) & 1) * 8 + ks * 16) * 2);
                uint32_t bh[4], bl[4];
                ldm_x4(bh, kaddr + OFF_KH * 2);
                ldm_x4(bl, kaddr + OFF_KL * 2);
                mma_bf16(S[2*ntp],   qh, bh);
                mma_bf16(S[2*ntp],   qh, bl);
                mma_bf16(S[2*ntp],   ql, bh);
                mma_bf16(S[2*ntp+1], qh, bh + 2);
                mma_bf16(S[2*ntp+1], qh, bl + 2);
                mma_bf16(S[2*ntp+1], ql, bh + 2);
            }
        }

        // ---- causal mask (diagonal tiles only) ----
        if (kt * 64 + 63 > qbase) {
            int q0 = qbase + (lane >> 2);
            int q1 = q0 + 8;
            #pragma unroll
            for (int nt = 0; nt < 8; nt++) {
                int k0 = kt * 64 + nt * 8 + (lane & 3) * 2;
                if (k0     > q0) S[nt][0] = -1e30f;
                if (k0 + 1 > q0) S[nt][1] = -1e30f;
                if (k0     > q1) S[nt][2] = -1e30f;
                if (k0 + 1 > q1) S[nt][3] = -1e30f;
            }
        }

        // ---- online softmax (quad reduction: lanes differ in bits 0-1) ----
        float mx0 = -1e30f, mx1 = -1e30f;
        #pragma unroll
        for (int nt = 0; nt < 8; nt++) {
            mx0 = fmaxf(mx0, fmaxf(S[nt][0], S[nt][1]));
            mx1 = fmaxf(mx1, fmaxf(S[nt][2], S[nt][3]));
        }
        mx0 = fmaxf(mx0, __shfl_xor_sync(0xffffffffu, mx0, 1));
        mx0 = fmaxf(mx0, __shfl_xor_sync(0xffffffffu, mx0, 2));
        mx1 = fmaxf(mx1, __shfl_xor_sync(0xffffffffu, mx1, 1));
        mx1 = fmaxf(mx1, __shfl_xor_sync(0xffffffffu, mx1, 2));
        float nm0 = fmaxf(m0, mx0), nm1 = fmaxf(m1, mx1);
        float c0 = __expf(m0 - nm0), c1 = __expf(m1 - nm1);
        float s0 = 0.f, s1 = 0.f;
        #pragma unroll
        for (int nt = 0; nt < 8; nt++) {
            S[nt][0] = __expf(S[nt][0] - nm0);
            S[nt][1] = __expf(S[nt][1] - nm0);
            S[nt][2] = __expf(S[nt][2] - nm1);
            S[nt][3] = __expf(S[nt][3] - nm1);
            s0 += S[nt][0] + S[nt][1];
            s1 += S[nt][2] + S[nt][3];
        }
        s0 += __shfl_xor_sync(0xffffffffu, s0, 1);
        s0 += __shfl_xor_sync(0xffffffffu, s0, 2);
        s1 += __shfl_xor_sync(0xffffffffu, s1, 1);
        s1 += __shfl_xor_sync(0xffffffffu, s1, 2);
        m0 = nm0; m1 = nm1;
        l0 = l0 * c0 + s0;
        l1 = l1 * c1 + s1;
        #pragma unroll
        for (int nt = 0; nt < 8; nt++) {
            O[nt][0] *= c0; O[nt][1] *= c0;
            O[nt][2] *= c1; O[nt][3] *= c1;
        }

        // ---- O += P * V (3-pass split; P frags repacked from S regs) ----
        #pragma unroll
        for (int g = 0; g < 4; g++) {
            uint32_t ah[4], al[4];
            packhl(S[2*g][0],   S[2*g][1],   ah[0], al[0]);
            packhl(S[2*g][2],   S[2*g][3],   ah[1], al[1]);
            packhl(S[2*g+1][0], S[2*g+1][1], ah[2], al[2]);
            packhl(S[2*g+1][2], S[2*g+1][3], ah[3], al[3]);
            #pragma unroll
            for (int ntp = 0; ntp < 4; ntp++) {
                uint32_t vaddr = sb + (uint32_t)(((g * 16 + (lane & 15)) * QS
                                  + ntp * 16 + ((lane >> 4) << 3)) * 2);
                uint32_t vh[4], vl[4];
                ldm_x4t(vh, vaddr + OFF_VH * 2);
                ldm_x4t(vl, vaddr + OFF_VL * 2);
                mma_bf16(O[2*ntp],   ah, vh);
                mma_bf16(O[2*ntp],   ah, vl);
                mma_bf16(O[2*ntp],   al, vh);
                mma_bf16(O[2*ntp+1], ah, vh + 2);
                mma_bf16(O[2*ntp+1], ah, vl + 2);
                mma_bf16(O[2*ntp+1], al, vh + 2);
            }
        }
    }

    // Finalize and write y [B*L, D] with col = h*64+hd
    float il0 = 1.f / l0, il1 = 1.f / l1;
    int rowg = qt * 128 + r0 + (lane >> 2);
    #pragma unroll
    for (int nt = 0; nt < 8; nt++) {
        int hd = nt * 8 + (lane & 3) * 2;
        float2 v0 = make_float2(O[nt][0] * il0, O[nt][1] * il0);
        float2 v1 = make_float2(O[nt][2] * il1, O[nt][3] * il1);
        *(float2*)(g_y + (size_t)(b * Ln + rowg) * Dn + h * 64 + hd) = v0;
        *(float2*)(g_y + (size_t)(b * Ln + rowg + 8) * Dn + h * 64 + hd) = v1;
    }
}

// ---------------------------------------------------------------------------
extern "C" void kernel_launch(void* const* d_in, const int* in_sizes, int n_in,
                              void* d_out, int out_size)
{
    (void)in_sizes; (void)n_in; (void)out_size;
    const float* x  = (const float*)d_in[0];
    const float* Wq = (const float*)d_in[1];
    const float* Wk = (const float*)d_in[2];
    const float* Wv = (const float*)d_in[3];
    const float* Wo = (const float*)d_in[4];
    float* out = (float*)d_out;

    cudaFuncSetAttribute(attn_kernel,
                         cudaFuncAttributeMaxDynamicSharedMemorySize,
                         ATTN_SMEM_BYTES);

    gemm_mma_kernel<<<dim3(Dn/64, NROW/128, 3), 256>>>(
        x, Wq, Wk, Wv, nullptr, 0);
    attn_kernel<<<dim3(Ln/128, Hn, Bn), 256, ATTN_SMEM_BYTES>>>();
    gemm_mma_kernel<<<dim3(Dn/64, NROW/128, 1), 256>>>(
        nullptr, Wo, Wo, Wo, out, 1);
}

// round 5
// speedup vs baseline: 2.4157x; 1.0172x over previous
#include <cuda_runtime.h>
#include <cuda_bf16.h>
#include <cstdint>

// Problem constants
constexpr int Bn  = 2;
constexpr int Ln  = 2048;
constexpr int Dn  = 1024;
constexpr int Hn  = 16;
constexpr int HDn = 64;
constexpr int NROW = Bn * Ln;   // 4096
constexpr size_t PLANE = (size_t)Bn * Hn * Ln * HDn;  // 4M elems

// Pre-split global scratch (bf16 stored as uint16)
__device__ uint16_t g_xh[(size_t)NROW * Dn];
__device__ uint16_t g_xl[(size_t)NROW * Dn];
__device__ uint16_t g_wh[(size_t)4 * Dn * Dn];   // slots: Wq,Wk,Wv,Wo
__device__ uint16_t g_wl[(size_t)4 * Dn * Dn];
__device__ uint16_t g_qkvh[3 * PLANE];           // [3][B][H][L][HD]
__device__ uint16_t g_qkvl[3 * PLANE];
__device__ uint16_t g_yh[(size_t)NROW * Dn];     // attn out, col = h*64+hd
__device__ uint16_t g_yl[(size_t)NROW * Dn];

// ---------------------------------------------------------------------------
// Helpers
// ---------------------------------------------------------------------------
__device__ __forceinline__ uint32_t s2u(const void* p) {
    uint32_t a;
    asm("{ .reg .u64 t; cvta.to.shared.u64 t, %1; cvt.u32.u64 %0, t; }"
        : "=r"(a) : "l"(p));
    return a;
}
__device__ __forceinline__ void ldm_x4(uint32_t* r, uint32_t a) {
    asm volatile("ldmatrix.sync.aligned.m8n8.x4.shared.b16 {%0,%1,%2,%3}, [%4];"
                 : "=r"(r[0]), "=r"(r[1]), "=r"(r[2]), "=r"(r[3]) : "r"(a));
}
__device__ __forceinline__ void ldm_x4t(uint32_t* r, uint32_t a) {
    asm volatile("ldmatrix.sync.aligned.m8n8.x4.trans.shared.b16 {%0,%1,%2,%3}, [%4];"
                 : "=r"(r[0]), "=r"(r[1]), "=r"(r[2]), "=r"(r[3]) : "r"(a));
}
__device__ __forceinline__ void mma_bf16(float* c, const uint32_t* a,
                                         const uint32_t* b) {
    asm volatile(
        "mma.sync.aligned.m16n8k16.row.col.f32.bf16.bf16.f32 "
        "{%0,%1,%2,%3}, {%4,%5,%6,%7}, {%8,%9}, {%0,%1,%2,%3};"
        : "+f"(c[0]), "+f"(c[1]), "+f"(c[2]), "+f"(c[3])
        : "r"(a[0]), "r"(a[1]), "r"(a[2]), "r"(a[3]), "r"(b[0]), "r"(b[1]));
}
__device__ __forceinline__ uint16_t bfu(float f) {
    __nv_bfloat16 h = __float2bfloat16_rn(f);
    return *(uint16_t*)&h;
}
__device__ __forceinline__ float bff(uint16_t u) {
    __nv_bfloat16 h = *(__nv_bfloat16*)&u;
    return __bfloat162float(h);
}
__device__ __forceinline__ void split4(float4 v, uint2& hi, uint2& lo) {
    uint16_t h0 = bfu(v.x), h1 = bfu(v.y), h2 = bfu(v.z), h3 = bfu(v.w);
    uint16_t l0 = bfu(v.x - bff(h0)), l1 = bfu(v.y - bff(h1));
    uint16_t l2 = bfu(v.z - bff(h2)), l3 = bfu(v.w - bff(h3));
    hi = make_uint2((uint32_t)h0 | ((uint32_t)h1 << 16),
                    (uint32_t)h2 | ((uint32_t)h3 << 16));
    lo = make_uint2((uint32_t)l0 | ((uint32_t)l1 << 16),
                    (uint32_t)l2 | ((uint32_t)l3 << 16));
}
__device__ __forceinline__ void packhl(float f0, float f1,
                                       uint32_t& h2, uint32_t& l2) {
    uint16_t h0 = bfu(f0), h1 = bfu(f1);
    uint16_t l0 = bfu(f0 - bff(h0)), l1 = bfu(f1 - bff(h1));
    h2 = (uint32_t)h0 | ((uint32_t)h1 << 16);
    l2 = (uint32_t)l0 | ((uint32_t)l1 << 16);
}

// ---------------------------------------------------------------------------
// One-shot split of x and all weights into bf16 hi/lo (2M float4 total)
// ---------------------------------------------------------------------------
__global__ void __launch_bounds__(256) split_kernel(
    const float* __restrict__ x,
    const float* __restrict__ Wq, const float* __restrict__ Wk,
    const float* __restrict__ Wv, const float* __restrict__ Wo)
{
    int i = blockIdx.x * blockDim.x + threadIdx.x;   // float4 index
    const float4* src;
    uint2 *dh, *dl;
    if (i < (1 << 20)) {
        src = (const float4*)x + i;
        dh = (uint2*)g_xh + i;
        dl = (uint2*)g_xl + i;
    } else {
        int j = i - (1 << 20);
        int slot = j >> 18;                // 0..3
        int off  = j & ((1 << 18) - 1);
        const float* w = (slot == 0) ? Wq : (slot == 1) ? Wk
                        : (slot == 2) ? Wv : Wo;
        src = (const float4*)w + off;
        dh = (uint2*)g_wh + ((size_t)slot << 18) + off;
        dl = (uint2*)g_wl + ((size_t)slot << 18) + off;
    }
    uint2 hi, lo;
    split4(*src, hi, lo);
    *dh = hi;
    *dl = lo;
}

// ---------------------------------------------------------------------------
// bf16-split GEMM v2: 128x128 CTA tile, 8 warps (2m x 4n), warp tile 64x32.
// ---------------------------------------------------------------------------
constexpr int AST = 40;    // A smem row stride elems
constexpr int BST = 136;   // B smem row stride elems

__global__ void __launch_bounds__(256, 1) gemm_mma_kernel(
    float* __restrict__ outp, int mode)
{
    __shared__ __align__(16) uint16_t Ah[128 * AST];
    __shared__ __align__(16) uint16_t Al[128 * AST];
    __shared__ __align__(16) uint16_t Bh[32 * BST];
    __shared__ __align__(16) uint16_t Bl[32 * BST];

    const int tid  = threadIdx.x;
    const int lane = tid & 31;
    const int w    = tid >> 5;
    const int wm   = w >> 2;        // 0..1
    const int wn   = w & 3;         // 0..3
    const int col0 = blockIdx.x * 128;
    const int row0 = blockIdx.y * 128;
    const int z    = blockIdx.z;

    const uint16_t* Aph = (mode == 0) ? g_xh : g_yh;
    const uint16_t* Apl = (mode == 0) ? g_xl : g_yl;
    const int slot = (mode == 0) ? z : 3;
    const uint16_t* Wph = g_wh + ((size_t)slot << 20);
    const uint16_t* Wpl = g_wl + ((size_t)slot << 20);

    float C[4][4][4];
    #pragma unroll
    for (int mi = 0; mi < 4; mi++)
        #pragma unroll
        for (int ni = 0; ni < 4; ni++)
            #pragma unroll
            for (int q = 0; q < 4; q++) C[mi][ni][q] = 0.f;

    uint4 apfh[2], apfl[2], bpfh[2], bpfl[2];
    #pragma unroll
    for (int i = 0; i < 2; i++) {
        int idx = tid + i * 256;
        int r = idx >> 2, c8 = idx & 3;
        size_t go = (size_t)(row0 + r) * Dn + c8 * 8;
        apfh[i] = *(const uint4*)(Aph + go);
        apfl[i] = *(const uint4*)(Apl + go);
    }
    #pragma unroll
    for (int i = 0; i < 2; i++) {
        int idx = tid + i * 256;
        int kk = idx >> 4, c8 = idx & 15;
        size_t go = (size_t)kk * Dn + col0 + c8 * 8;
        bpfh[i] = *(const uint4*)(Wph + go);
        bpfl[i] = *(const uint4*)(Wpl + go);
    }

    const uint32_t ah_s = s2u(Ah), al_s = s2u(Al);
    const uint32_t bh_s = s2u(Bh), bl_s = s2u(Bl);

    for (int c = 0; c < 32; c++) {
        #pragma unroll
        for (int i = 0; i < 2; i++) {
            int idx = tid + i * 256;
            int r = idx >> 2, c8 = idx & 3;
            *(uint4*)(Ah + r * AST + c8 * 8) = apfh[i];
            *(uint4*)(Al + r * AST + c8 * 8) = apfl[i];
        }
        #pragma unroll
        for (int i = 0; i < 2; i++) {
            int idx = tid + i * 256;
            int kk = idx >> 4, c8 = idx & 15;
            *(uint4*)(Bh + kk * BST + c8 * 8) = bpfh[i];
            *(uint4*)(Bl + kk * BST + c8 * 8) = bpfl[i];
        }
        __syncthreads();

        if (c < 31) {
            const int k0 = (c + 1) * 32;
            #pragma unroll
            for (int i = 0; i < 2; i++) {
                int idx = tid + i * 256;
                int r = idx >> 2, c8 = idx & 3;
                size_t go = (size_t)(row0 + r) * Dn + k0 + c8 * 8;
                apfh[i] = *(const uint4*)(Aph + go);
                apfl[i] = *(const uint4*)(Apl + go);
            }
            #pragma unroll
            for (int i = 0; i < 2; i++) {
                int idx = tid + i * 256;
                int kk = idx >> 4, c8 = idx & 15;
                size_t go = (size_t)(k0 + kk) * Dn + col0 + c8 * 8;
                bpfh[i] = *(const uint4*)(Wph + go);
                bpfl[i] = *(const uint4*)(Wpl + go);
            }
        }

        #pragma unroll
        for (int ks = 0; ks < 2; ks++) {
            uint32_t ahf[4][4], alf[4][4], bhf[4][2], blf[4][2];
            #pragma unroll
            for (int mi = 0; mi < 4; mi++) {
                uint32_t off = (uint32_t)((wm * 64 + mi * 16 + (lane & 15)) * (AST * 2)
                                          + ks * 32 + ((lane >> 4) * 16));
                ldm_x4(ahf[mi], ah_s + off);
                ldm_x4(alf[mi], al_s + off);
            }
            #pragma unroll
            for (int g = 0; g < 2; g++) {
                uint32_t off = (uint32_t)((ks * 16 + (lane & 15)) * (BST * 2)
                                          + (wn * 32 + g * 16 + ((lane >> 4) * 8)) * 2);
                uint32_t t[4];
                ldm_x4t(t, bh_s + off);
                bhf[g*2][0] = t[0]; bhf[g*2][1] = t[1];
                bhf[g*2+1][0] = t[2]; bhf[g*2+1][1] = t[3];
                ldm_x4t(t, bl_s + off);
                blf[g*2][0] = t[0]; blf[g*2][1] = t[1];
                blf[g*2+1][0] = t[2]; blf[g*2+1][1] = t[3];
            }
            #pragma unroll
            for (int mi = 0; mi < 4; mi++)
                #pragma unroll
                for (int ni = 0; ni < 4; ni++) {
                    mma_bf16(C[mi][ni], ahf[mi], bhf[ni]);
                    mma_bf16(C[mi][ni], ahf[mi], blf[ni]);
                    mma_bf16(C[mi][ni], alf[mi], bhf[ni]);
                }
        }
        __syncthreads();
    }

    #pragma unroll
    for (int mi = 0; mi < 4; mi++)
        #pragma unroll
        for (int ni = 0; ni < 4; ni++) {
            int row = row0 + wm * 64 + mi * 16 + (lane >> 2);
            int col = col0 + wn * 32 + ni * 8 + (lane & 3) * 2;
            if (mode == 0) {
                uint16_t* qh = g_qkvh + (size_t)z * PLANE;
                uint16_t* ql = g_qkvl + (size_t)z * PLANE;
                float s = (z == 0) ? 0.125f : 1.f;
                int hh = col >> 6, hd = col & 63;
                #pragma unroll
                for (int half = 0; half < 2; half++) {
                    int r = row + half * 8;
                    int b = r >> 11, l = r & 2047;
                    size_t off = (((size_t)(b * Hn + hh) * Ln + l) << 6) + hd;
                    uint32_t hw, lw;
                    packhl(C[mi][ni][half*2] * s, C[mi][ni][half*2+1] * s, hw, lw);
                    *(uint32_t*)(qh + off) = hw;
                    *(uint32_t*)(ql + off) = lw;
                }
            } else {
                float2 v0 = make_float2(C[mi][ni][0], C[mi][ni][1]);
                float2 v1 = make_float2(C[mi][ni][2], C[mi][ni][3]);
                *(float2*)(outp + (size_t)row * Dn + col) = v0;
                *(float2*)(outp + (size_t)(row + 8) * Dn + col) = v1;
            }
        }
}

// ---------------------------------------------------------------------------
// Tensor-core flash attention (pre-split bf16 Q/K/V; Q pre-scaled).
// ---------------------------------------------------------------------------
constexpr int QS = 72;
constexpr int OFF_QH = 0;
constexpr int OFF_QL = 128 * QS;
constexpr int OFF_KH = 2 * 128 * QS;
constexpr int OFF_KL = OFF_KH + 64 * QS;
constexpr int OFF_VH = OFF_KL + 64 * QS;
constexpr int OFF_VL = OFF_VH + 64 * QS;
constexpr int ATTN_SMEM_BYTES = (OFF_VL + 64 * QS) * 2;  // 73,728

__global__ void __launch_bounds__(256) attn_kernel()
{
    extern __shared__ uint16_t smh[];

    const int qt   = blockIdx.x;
    const int h    = blockIdx.y;
    const int b    = blockIdx.z;
    const int tid  = threadIdx.x;
    const int lane = tid & 31;
    const int wid  = tid >> 5;
    const int r0   = wid * 16;

    const size_t base = ((size_t)(b * Hn + h) * Ln) * HDn;
    const uint16_t* qh_g = g_qkvh + base;
    const uint16_t* ql_g = g_qkvl + base;
    const uint16_t* kh_g = g_qkvh + PLANE + base;
    const uint16_t* kl_g = g_qkvl + PLANE + base;
    const uint16_t* vh_g = g_qkvh + 2 * PLANE + base;
    const uint16_t* vl_g = g_qkvl + 2 * PLANE + base;

    const uint32_t sb = s2u(smh);

    #pragma unroll
    for (int i = 0; i < 4; i++) {
        int idx = tid + i * 256;
        int r = idx >> 3, c8 = idx & 7;
        size_t go = (size_t)(qt * 128 + r) * HDn + c8 * 8;
        *(uint4*)(smh + OFF_QH + r * QS + c8 * 8) = *(const uint4*)(qh_g + go);
        *(uint4*)(smh + OFF_QL + r * QS + c8 * 8) = *(const uint4*)(ql_g + go);
    }

    float m0 = -1e30f, m1 = -1e30f, l0 = 0.f, l1 = 0.f;
    float O[8][4];
    #pragma unroll
    for (int nt = 0; nt < 8; nt++)
        #pragma unroll
        for (int q = 0; q < 4; q++) O[nt][q] = 0.f;

    const int qbase = qt * 128 + r0;
    const int ktmax = 2 * qt + 2;

    for (int kt = 0; kt < ktmax; kt++) {
        __syncthreads();
        #pragma unroll
        for (int i = 0; i < 2; i++) {
            int idx = tid + i * 256;
            int r = idx >> 3, c8 = idx & 7;
            size_t go = (size_t)(kt * 64 + r) * HDn + c8 * 8;
            *(uint4*)(smh + OFF_KH + r * QS + c8 * 8) = *(const uint4*)(kh_g + go);
            *(uint4*)(smh + OFF_KL + r * QS + c8 * 8) = *(const uint4*)(kl_g + go);
            *(uint4*)(smh + OFF_VH + r * QS + c8 * 8) = *(const uint4*)(vh_g + go);
            *(uint4*)(smh + OFF_VL + r * QS + c8 * 8) = *(const uint4*)(vl_g + go);
        }
        __syncthreads();

        if (kt * 64 > qbase + 15) continue;

        float S[8][4];
        #pragma unroll
        for (int nt = 0; nt < 8; nt++)
            #pragma unroll
            for (int q = 0; q < 4; q++) S[nt][q] = 0.f;

        #pragma unroll
        for (int ks = 0; ks < 4; ks++) {
            uint32_t qh[4], ql[4];
            uint32_t qaddr = sb + (uint32_t)(((r0 + (lane & 15)) * QS
                              + ks * 16 + ((lane >> 4) * 8)) * 2);
            ldm_x4(qh, qaddr + OFF_QH * 2);
            ldm_x4(ql, qaddr + OFF_QL * 2);
            #pragma unroll
            for (int ntp = 0; ntp < 4; ntp++) {
                uint32_t kaddr = sb + (uint32_t)(((ntp * 16 + (lane & 7)
                                  + ((lane >> 4) << 3)) * QS
                                  + ((lane >> 3) & 1) * 8 + ks * 16) * 2);
                uint32_t bh[4], bl[4];
                ldm_x4(bh, kaddr + OFF_KH * 2);
                ldm_x4(bl, kaddr + OFF_KL * 2);
                mma_bf16(S[2*ntp],   qh, bh);
                mma_bf16(S[2*ntp],   qh, bl);
                mma_bf16(S[2*ntp],   ql, bh);
                mma_bf16(S[2*ntp+1], qh, bh + 2);
                mma_bf16(S[2*ntp+1], qh, bl + 2);
                mma_bf16(S[2*ntp+1], ql, bh + 2);
            }
        }

        if (kt * 64 + 63 > qbase) {
            int q0 = qbase + (lane >> 2);
            int q1 = q0 + 8;
            #pragma unroll
            for (int nt = 0; nt < 8; nt++) {
                int k0 = kt * 64 + nt * 8 + (lane & 3) * 2;
                if (k0     > q0) S[nt][0] = -1e30f;
                if (k0 + 1 > q0) S[nt][1] = -1e30f;
                if (k0     > q1) S[nt][2] = -1e30f;
                if (k0 + 1 > q1) S[nt][3] = -1e30f;
            }
        }

        float mx0 = -1e30f, mx1 = -1e30f;
        #pragma unroll
        for (int nt = 0; nt < 8; nt++) {
            mx0 = fmaxf(mx0, fmaxf(S[nt][0], S[nt][1]));
            mx1 = fmaxf(mx1, fmaxf(S[nt][2], S[nt][3]));
        }
        mx0 = fmaxf(mx0, __shfl_xor_sync(0xffffffffu, mx0, 1));
        mx0 = fmaxf(mx0, __shfl_xor_sync(0xffffffffu, mx0, 2));
        mx1 = fmaxf(mx1, __shfl_xor_sync(0xffffffffu, mx1, 1));
        mx1 = fmaxf(mx1, __shfl_xor_sync(0xffffffffu, mx1, 2));
        float nm0 = fmaxf(m0, mx0), nm1 = fmaxf(m1, mx1);
        float c0 = __expf(m0 - nm0), c1 = __expf(m1 - nm1);
        float s0 = 0.f, s1 = 0.f;
        #pragma unroll
        for (int nt = 0; nt < 8; nt++) {
            S[nt][0] = __expf(S[nt][0] - nm0);
            S[nt][1] = __expf(S[nt][1] - nm0);
            S[nt][2] = __expf(S[nt][2] - nm1);
            S[nt][3] = __expf(S[nt][3] - nm1);
            s0 += S[nt][0] + S[nt][1];
            s1 += S[nt][2] + S[nt][3];
        }
        s0 += __shfl_xor_sync(0xffffffffu, s0, 1);
        s0 += __shfl_xor_sync(0xffffffffu, s0, 2);
        s1 += __shfl_xor_sync(0xffffffffu, s1, 1);
        s1 += __shfl_xor_sync(0xffffffffu, s1, 2);
        m0 = nm0; m1 = nm1;
        l0 = l0 * c0 + s0;
        l1 = l1 * c1 + s1;
        #pragma unroll
        for (int nt = 0; nt < 8; nt++) {
            O[nt][0] *= c0; O[nt][1] *= c0;
            O[nt][2] *= c1; O[nt][3] *= c1;
        }

        #pragma unroll
        for (int g = 0; g < 4; g++) {
            uint32_t ah[4], al[4];
            packhl(S[2*g][0],   S[2*g][1],   ah[0], al[0]);
            packhl(S[2*g][2],   S[2*g][3],   ah[1], al[1]);
            packhl(S[2*g+1][0], S[2*g+1][1], ah[2], al[2]);
            packhl(S[2*g+1][2], S[2*g+1][3], ah[3], al[3]);
            #pragma unroll
            for (int ntp = 0; ntp < 4; ntp++) {
                uint32_t vaddr = sb + (uint32_t)(((g * 16 + (lane & 15)) * QS
                                  + ntp * 16 + ((lane >> 4) << 3)) * 2);
                uint32_t vh[4], vl[4];
                ldm_x4t(vh, vaddr + OFF_VH * 2);
                ldm_x4t(vl, vaddr + OFF_VL * 2);
                mma_bf16(O[2*ntp],   ah, vh);
                mma_bf16(O[2*ntp],   ah, vl);
                mma_bf16(O[2*ntp],   al, vh);
                mma_bf16(O[2*ntp+1], ah, vh + 2);
                mma_bf16(O[2*ntp+1], ah, vl + 2);
                mma_bf16(O[2*ntp+1], al, vh + 2);
            }
        }
    }

    float il0 = 1.f / l0, il1 = 1.f / l1;
    int rowg = qt * 128 + r0 + (lane >> 2);
    #pragma unroll
    for (int nt = 0; nt < 8; nt++) {
        int hd = nt * 8 + (lane & 3) * 2;
        size_t o0 = (size_t)(b * Ln + rowg) * Dn + h * 64 + hd;
        size_t o1 = (size_t)(b * Ln + rowg + 8) * Dn + h * 64 + hd;
        uint32_t hw, lw;
        packhl(O[nt][0] * il0, O[nt][1] * il0, hw, lw);
        *(uint32_t*)(g_yh + o0) = hw;
        *(uint32_t*)(g_yl + o0) = lw;
        packhl(O[nt][2] * il1, O[nt][3] * il1, hw, lw);
        *(uint32_t*)(g_yh + o1) = hw;
        *(uint32_t*)(g_yl + o1) = lw;
    }
}

// ---------------------------------------------------------------------------
extern "C" void kernel_launch(void* const* d_in, const int* in_sizes, int n_in,
                              void* d_out, int out_size)
{
    (void)in_sizes; (void)n_in; (void)out_size;
    const float* x  = (const float*)d_in[0];
    const float* Wq = (const float*)d_in[1];
    const float* Wk = (const float*)d_in[2];
    const float* Wv = (const float*)d_in[3];
    const float* Wo = (const float*)d_in[4];
    float* out = (float*)d_out;

    cudaFuncSetAttribute(attn_kernel,
                         cudaFuncAttributeMaxDynamicSharedMemorySize,
                         ATTN_SMEM_BYTES);

    split_kernel<<<8192, 256>>>(x, Wq, Wk, Wv, Wo);
    gemm_mma_kernel<<<dim3(Dn/128, NROW/128, 3), 256>>>(nullptr, 0);
    attn_kernel<<<dim3(Ln/128, Hn, Bn), 256, ATTN_SMEM_BYTES>>>();
    gemm_mma_kernel<<<dim3(Dn/128, NROW/128, 1), 256>>>(out, 1);
}

// round 6
// speedup vs baseline: 2.6069x; 1.0792x over previous
#include <cuda_runtime.h>
#include <cuda_bf16.h>
#include <cstdint>

// Problem constants
constexpr int Bn  = 2;
constexpr int Ln  = 2048;
constexpr int Dn  = 1024;
constexpr int Hn  = 16;
constexpr int HDn = 64;
constexpr int NROW = Bn * Ln;   // 4096
constexpr size_t PLANE = (size_t)Bn * Hn * Ln * HDn;  // 4M elems

// Pre-split global scratch (bf16 stored as uint16)
__device__ uint16_t g_xh[(size_t)NROW * Dn];
__device__ uint16_t g_xl[(size_t)NROW * Dn];
__device__ uint16_t g_wh[(size_t)4 * Dn * Dn];   // slots: Wq,Wk,Wv,Wo
__device__ uint16_t g_wl[(size_t)4 * Dn * Dn];
__device__ uint16_t g_qkvh[3 * PLANE];           // [3][B][H][L][HD]
__device__ uint16_t g_qkvl[3 * PLANE];
__device__ uint16_t g_yh[(size_t)NROW * Dn];     // attn out, col = h*64+hd
__device__ uint16_t g_yl[(size_t)NROW * Dn];

// ---------------------------------------------------------------------------
// Helpers
// ---------------------------------------------------------------------------
__device__ __forceinline__ uint32_t s2u(const void* p) {
    uint32_t a;
    asm("{ .reg .u64 t; cvta.to.shared.u64 t, %1; cvt.u32.u64 %0, t; }"
        : "=r"(a) : "l"(p));
    return a;
}
__device__ __forceinline__ void cp16(uint32_t dst, const void* src) {
    asm volatile("cp.async.cg.shared.global [%0], [%1], 16;"
                 :: "r"(dst), "l"(src) : "memory");
}
#define CP_COMMIT() asm volatile("cp.async.commit_group;" ::: "memory")
#define CP_WAIT0()  asm volatile("cp.async.wait_group 0;" ::: "memory")

__device__ __forceinline__ void ldm_x4(uint32_t* r, uint32_t a) {
    asm volatile("ldmatrix.sync.aligned.m8n8.x4.shared.b16 {%0,%1,%2,%3}, [%4];"
                 : "=r"(r[0]), "=r"(r[1]), "=r"(r[2]), "=r"(r[3]) : "r"(a));
}
__device__ __forceinline__ void ldm_x4t(uint32_t* r, uint32_t a) {
    asm volatile("ldmatrix.sync.aligned.m8n8.x4.trans.shared.b16 {%0,%1,%2,%3}, [%4];"
                 : "=r"(r[0]), "=r"(r[1]), "=r"(r[2]), "=r"(r[3]) : "r"(a));
}
__device__ __forceinline__ void mma_bf16(float* c, const uint32_t* a,
                                         const uint32_t* b) {
    asm volatile(
        "mma.sync.aligned.m16n8k16.row.col.f32.bf16.bf16.f32 "
        "{%0,%1,%2,%3}, {%4,%5,%6,%7}, {%8,%9}, {%0,%1,%2,%3};"
        : "+f"(c[0]), "+f"(c[1]), "+f"(c[2]), "+f"(c[3])
        : "r"(a[0]), "r"(a[1]), "r"(a[2]), "r"(a[3]), "r"(b[0]), "r"(b[1]));
}
__device__ __forceinline__ uint16_t bfu(float f) {
    __nv_bfloat16 h = __float2bfloat16_rn(f);
    return *(uint16_t*)&h;
}
__device__ __forceinline__ float bff(uint16_t u) {
    __nv_bfloat16 h = *(__nv_bfloat16*)&u;
    return __bfloat162float(h);
}
__device__ __forceinline__ void split4(float4 v, uint2& hi, uint2& lo) {
    uint16_t h0 = bfu(v.x), h1 = bfu(v.y), h2 = bfu(v.z), h3 = bfu(v.w);
    uint16_t l0 = bfu(v.x - bff(h0)), l1 = bfu(v.y - bff(h1));
    uint16_t l2 = bfu(v.z - bff(h2)), l3 = bfu(v.w - bff(h3));
    hi = make_uint2((uint32_t)h0 | ((uint32_t)h1 << 16),
                    (uint32_t)h2 | ((uint32_t)h3 << 16));
    lo = make_uint2((uint32_t)l0 | ((uint32_t)l1 << 16),
                    (uint32_t)l2 | ((uint32_t)l3 << 16));
}
__device__ __forceinline__ void packhl(float f0, float f1,
                                       uint32_t& h2, uint32_t& l2) {
    uint16_t h0 = bfu(f0), h1 = bfu(f1);
    uint16_t l0 = bfu(f0 - bff(h0)), l1 = bfu(f1 - bff(h1));
    h2 = (uint32_t)h0 | ((uint32_t)h1 << 16);
    l2 = (uint32_t)l0 | ((uint32_t)l1 << 16);
}

// ---------------------------------------------------------------------------
// One-shot split of x and all weights into bf16 hi/lo
// ---------------------------------------------------------------------------
__global__ void __launch_bounds__(256) split_kernel(
    const float* __restrict__ x,
    const float* __restrict__ Wq, const float* __restrict__ Wk,
    const float* __restrict__ Wv, const float* __restrict__ Wo)
{
    int i = blockIdx.x * blockDim.x + threadIdx.x;   // float4 index
    const float4* src;
    uint2 *dh, *dl;
    if (i < (1 << 20)) {
        src = (const float4*)x + i;
        dh = (uint2*)g_xh + i;
        dl = (uint2*)g_xl + i;
    } else {
        int j = i - (1 << 20);
        int slot = j >> 18;
        int off  = j & ((1 << 18) - 1);
        const float* w = (slot == 0) ? Wq : (slot == 1) ? Wk
                        : (slot == 2) ? Wv : Wo;
        src = (const float4*)w + off;
        dh = (uint2*)g_wh + ((size_t)slot << 18) + off;
        dl = (uint2*)g_wl + ((size_t)slot << 18) + off;
    }
    uint2 hi, lo;
    split4(*src, hi, lo);
    *dh = hi;
    *dl = lo;
}

// ---------------------------------------------------------------------------
// bf16-split GEMM v3: 128x64 CTA tile, 8 warps (4m x 2n), warp tile 32x32.
// cp.async 2-stage pipeline, pre-split inputs, 2 CTAs/SM.
// Stage layout (bytes): Ah 0 (10240), Al 10240, Bh 20480 (4608), Bl 25088.
// Stage size 29696 B, 2 stages = 59392 B dynamic smem.
// ---------------------------------------------------------------------------
constexpr int G_STAGE = 29696;
constexpr int GEMM_SMEM_BYTES = 2 * G_STAGE;

__global__ void __launch_bounds__(256, 2) gemm_mma_kernel(
    float* __restrict__ outp, int mode)
{
    extern __shared__ uint16_t smg[];
    const uint32_t sb = s2u(smg);

    const int tid  = threadIdx.x;
    const int lane = tid & 31;
    const int w    = tid >> 5;
    const int wm   = w & 3;         // 4 m-groups of 32
    const int wn   = w >> 2;        // 2 n-groups of 32
    const int col0 = blockIdx.x * 64;
    const int row0 = blockIdx.y * 128;
    const int z    = blockIdx.z;

    const uint16_t* Aph = (mode == 0) ? g_xh : g_yh;
    const uint16_t* Apl = (mode == 0) ? g_xl : g_yl;
    const int slot = (mode == 0) ? z : 3;
    const uint16_t* Wph = g_wh + ((size_t)slot << 20);
    const uint16_t* Wpl = g_wl + ((size_t)slot << 20);

    float C[2][4][4];
    #pragma unroll
    for (int mi = 0; mi < 2; mi++)
        #pragma unroll
        for (int ni = 0; ni < 4; ni++)
            #pragma unroll
            for (int q = 0; q < 4; q++) C[mi][ni][q] = 0.f;

    // cp.async issue of one k-stage
    auto issue = [&](int c_, int s_) {
        uint32_t dstb = sb + s_ * G_STAGE;
        int k0 = c_ * 32;
        // A hi/lo: 4 x 256 chunks
        #pragma unroll
        for (int i = 0; i < 4; i++) {
            int hil = i >> 1;
            int local = (i & 1) * 256 + tid;
            int r = local >> 2, cc = local & 3;
            uint32_t dst = dstb + hil * 10240u + (uint32_t)(r * 40 + cc * 8) * 2;
            const uint16_t* src = (hil ? Apl : Aph)
                                  + (size_t)(row0 + r) * Dn + k0 + cc * 8;
            cp16(dst, src);
        }
        // B hi/lo: 2 x 256 chunks
        #pragma unroll
        for (int i = 0; i < 2; i++) {
            int kk = tid >> 3, cc = tid & 7;
            uint32_t dst = dstb + 20480u + i * 4608u
                           + (uint32_t)(kk * 72 + cc * 8) * 2;
            const uint16_t* src = (i ? Wpl : Wph)
                                  + (size_t)(k0 + kk) * Dn + col0 + cc * 8;
            cp16(dst, src);
        }
    };

    issue(0, 0);
    CP_COMMIT();

    for (int c = 0; c < 32; c++) {
        CP_WAIT0();
        __syncthreads();
        if (c + 1 < 32) {
            issue(c + 1, (c + 1) & 1);
            CP_COMMIT();
        }
        const uint32_t stgb = sb + (c & 1) * G_STAGE;

        #pragma unroll
        for (int ks = 0; ks < 2; ks++) {
            uint32_t ahf[2][4], alf[2][4], bhf[4][2], blf[4][2];
            #pragma unroll
            for (int mi = 0; mi < 2; mi++) {
                uint32_t off = (uint32_t)((wm * 32 + mi * 16 + (lane & 15)) * 80
                                          + ks * 32 + ((lane >> 4) * 16));
                ldm_x4(ahf[mi], stgb + off);
                ldm_x4(alf[mi], stgb + 10240u + off);
            }
            #pragma unroll
            for (int g = 0; g < 2; g++) {
                uint32_t off = 20480u
                    + (uint32_t)((ks * 16 + (lane & 15)) * 144
                                 + (wn * 32 + g * 16 + ((lane >> 4) * 8)) * 2);
                uint32_t t[4];
                ldm_x4t(t, stgb + off);
                bhf[g*2][0] = t[0]; bhf[g*2][1] = t[1];
                bhf[g*2+1][0] = t[2]; bhf[g*2+1][1] = t[3];
                ldm_x4t(t, stgb + 4608u + off);
                blf[g*2][0] = t[0]; blf[g*2][1] = t[1];
                blf[g*2+1][0] = t[2]; blf[g*2+1][1] = t[3];
            }
            #pragma unroll
            for (int mi = 0; mi < 2; mi++)
                #pragma unroll
                for (int ni = 0; ni < 4; ni++) {
                    mma_bf16(C[mi][ni], ahf[mi], bhf[ni]);
                    mma_bf16(C[mi][ni], ahf[mi], blf[ni]);
                    mma_bf16(C[mi][ni], alf[mi], bhf[ni]);
                }
        }
        __syncthreads();
    }

    #pragma unroll
    for (int mi = 0; mi < 2; mi++)
        #pragma unroll
        for (int ni = 0; ni < 4; ni++) {
            int row = row0 + wm * 32 + mi * 16 + (lane >> 2);
            int col = col0 + wn * 32 + ni * 8 + (lane & 3) * 2;
            if (mode == 0) {
                uint16_t* qh = g_qkvh + (size_t)z * PLANE;
                uint16_t* ql = g_qkvl + (size_t)z * PLANE;
                float s = (z == 0) ? 0.125f : 1.f;
                int hh = col >> 6, hd = col & 63;
                #pragma unroll
                for (int half = 0; half < 2; half++) {
                    int r = row + half * 8;
                    int b = r >> 11, l = r & 2047;
                    size_t off = (((size_t)(b * Hn + hh) * Ln + l) << 6) + hd;
                    uint32_t hw, lw;
                    packhl(C[mi][ni][half*2] * s, C[mi][ni][half*2+1] * s, hw, lw);
                    *(uint32_t*)(qh + off) = hw;
                    *(uint32_t*)(ql + off) = lw;
                }
            } else {
                float2 v0 = make_float2(C[mi][ni][0], C[mi][ni][1]);
                float2 v1 = make_float2(C[mi][ni][2], C[mi][ni][3]);
                *(float2*)(outp + (size_t)row * Dn + col) = v0;
                *(float2*)(outp + (size_t)(row + 8) * Dn + col) = v1;
            }
        }
}

// ---------------------------------------------------------------------------
// Tensor-core flash attention v2: Q frags register-resident, KV double-
// buffered via cp.async. Q's staging region doubles as KV stage 1.
// Stage (bytes): KH 0 (9216), KL 9216, VH 18432, VL 27648; size 36864.
// Q: QH at 36864 (stage1 base), QL at 36864+18432.
// ---------------------------------------------------------------------------
constexpr int QS = 72;                 // elems per row
constexpr int A_STAGE = 36864;         // bytes
constexpr int ATTN_SMEM_BYTES = 2 * A_STAGE;   // 73,728

__global__ void __launch_bounds__(256) attn_kernel()
{
    extern __shared__ uint16_t smh[];
    const uint32_t sb = s2u(smh);

    const int qt   = blockIdx.x;
    const int h    = blockIdx.y;
    const int b    = blockIdx.z;
    const int tid  = threadIdx.x;
    const int lane = tid & 31;
    const int wid  = tid >> 5;
    const int r0   = wid * 16;

    const size_t base = ((size_t)(b * Hn + h) * Ln) * HDn;
    const uint16_t* qh_g = g_qkvh + base;
    const uint16_t* ql_g = g_qkvl + base;
    const uint16_t* kh_g = g_qkvh + PLANE + base;
    const uint16_t* kl_g = g_qkvl + PLANE + base;
    const uint16_t* vh_g = g_qkvh + 2 * PLANE + base;
    const uint16_t* vl_g = g_qkvl + 2 * PLANE + base;

    // Load Q tile [128][64] hi/lo into stage-1 region (elems 18432 / 27648)
    #pragma unroll
    for (int i = 0; i < 4; i++) {
        int idx = tid + i * 256;
        int r = idx >> 3, c8 = idx & 7;
        size_t go = (size_t)(qt * 128 + r) * HDn + c8 * 8;
        *(uint4*)(smh + 18432 + r * QS + c8 * 8) = *(const uint4*)(qh_g + go);
        *(uint4*)(smh + 27648 + r * QS + c8 * 8) = *(const uint4*)(ql_g + go);
    }

    const int ktmax = 2 * qt + 2;

    // Issue KV stage 0 while Q settles
    auto issue_kv = [&](int kt_, int s_) {
        uint32_t dstb = sb + s_ * A_STAGE;
        #pragma unroll
        for (int i = 0; i < 8; i++) {
            int p = i >> 1;
            int local = (i & 1) * 256 + tid;
            int r = local >> 3, cc = local & 7;
            uint32_t dst = dstb + p * 9216u + (uint32_t)(r * QS + cc * 8) * 2;
            const uint16_t* gp = (p == 0) ? kh_g : (p == 1) ? kl_g
                                : (p == 2) ? vh_g : vl_g;
            cp16(dst, gp + (size_t)(kt_ * 64 + r) * HDn + cc * 8);
        }
    };
    issue_kv(0, 0);
    CP_COMMIT();
    __syncthreads();

    // Extract Q fragments to registers (reused every kt iteration)
    uint32_t qfh[4][4], qfl[4][4];
    #pragma unroll
    for (int ks = 0; ks < 4; ks++) {
        uint32_t qaddr = sb + (uint32_t)((18432 + (r0 + (lane & 15)) * QS
                          + ks * 16 + ((lane >> 4) * 8)) * 2);
        ldm_x4(qfh[ks], qaddr);
        ldm_x4(qfl[ks], qaddr + 9216u * 2);
    }
    __syncthreads();   // Q consumed; stage-1 region may be overwritten

    float m0 = -1e30f, m1 = -1e30f, l0 = 0.f, l1 = 0.f;
    float O[8][4];
    #pragma unroll
    for (int nt = 0; nt < 8; nt++)
        #pragma unroll
        for (int q = 0; q < 4; q++) O[nt][q] = 0.f;

    const int qbase = qt * 128 + r0;

    for (int kt = 0; kt < ktmax; kt++) {
        CP_WAIT0();
        __syncthreads();
        if (kt + 1 < ktmax) {
            issue_kv(kt + 1, (kt + 1) & 1);
            CP_COMMIT();
        }

        if (kt * 64 > qbase + 15) continue;

        const uint32_t stgb = sb + (kt & 1) * A_STAGE;

        // ---- S = Q * K^T (3-pass split) ----
        float S[8][4];
        #pragma unroll
        for (int nt = 0; nt < 8; nt++)
            #pragma unroll
            for (int q = 0; q < 4; q++) S[nt][q] = 0.f;

        #pragma unroll
        for (int ks = 0; ks < 4; ks++) {
            #pragma unroll
            for (int ntp = 0; ntp < 4; ntp++) {
                uint32_t kaddr = stgb + (uint32_t)(((ntp * 16 + (lane & 7)
                                  + ((lane >> 4) << 3)) * QS
                                  + ((lane >> 3) & 1) * 8 + ks * 16) * 2);
                uint32_t bh[4], bl[4];
                ldm_x4(bh, kaddr);            // KH at stage offset 0
                ldm_x4(bl, kaddr + 9216u);    // KL
                mma_bf16(S[2*ntp],   qfh[ks], bh);
                mma_bf16(S[2*ntp],   qfh[ks], bl);
                mma_bf16(S[2*ntp],   qfl[ks], bh);
                mma_bf16(S[2*ntp+1], qfh[ks], bh + 2);
                mma_bf16(S[2*ntp+1], qfh[ks], bl + 2);
                mma_bf16(S[2*ntp+1], qfl[ks], bh + 2);
            }
        }

        // ---- causal mask (diagonal tiles only) ----
        if (kt * 64 + 63 > qbase) {
            int q0 = qbase + (lane >> 2);
            int q1 = q0 + 8;
            #pragma unroll
            for (int nt = 0; nt < 8; nt++) {
                int k0 = kt * 64 + nt * 8 + (lane & 3) * 2;
                if (k0     > q0) S[nt][0] = -1e30f;
                if (k0 + 1 > q0) S[nt][1] = -1e30f;
                if (k0     > q1) S[nt][2] = -1e30f;
                if (k0 + 1 > q1) S[nt][3] = -1e30f;
            }
        }

        // ---- online softmax ----
        float mx0 = -1e30f, mx1 = -1e30f;
        #pragma unroll
        for (int nt = 0; nt < 8; nt++) {
            mx0 = fmaxf(mx0, fmaxf(S[nt][0], S[nt][1]));
            mx1 = fmaxf(mx1, fmaxf(S[nt][2], S[nt][3]));
        }
        mx0 = fmaxf(mx0, __shfl_xor_sync(0xffffffffu, mx0, 1));
        mx0 = fmaxf(mx0, __shfl_xor_sync(0xffffffffu, mx0, 2));
        mx1 = fmaxf(mx1, __shfl_xor_sync(0xffffffffu, mx1, 1));
        mx1 = fmaxf(mx1, __shfl_xor_sync(0xffffffffu, mx1, 2));
        float nm0 = fmaxf(m0, mx0), nm1 = fmaxf(m1, mx1);
        float c0 = __expf(m0 - nm0), c1 = __expf(m1 - nm1);
        float s0 = 0.f, s1 = 0.f;
        #pragma unroll
        for (int nt = 0; nt < 8; nt++) {
            S[nt][0] = __expf(S[nt][0] - nm0);
            S[nt][1] = __expf(S[nt][1] - nm0);
            S[nt][2] = __expf(S[nt][2] - nm1);
            S[nt][3] = __expf(S[nt][3] - nm1);
            s0 += S[nt][0] + S[nt][1];
            s1 += S[nt][2] + S[nt][3];
        }
        s0 += __shfl_xor_sync(0xffffffffu, s0, 1);
        s0 += __shfl_xor_sync(0xffffffffu, s0, 2);
        s1 += __shfl_xor_sync(0xffffffffu, s1, 1);
        s1 += __shfl_xor_sync(0xffffffffu, s1, 2);
        m0 = nm0; m1 = nm1;
        l0 = l0 * c0 + s0;
        l1 = l1 * c1 + s1;
        #pragma unroll
        for (int nt = 0; nt < 8; nt++) {
            O[nt][0] *= c0; O[nt][1] *= c0;
            O[nt][2] *= c1; O[nt][3] *= c1;
        }

        // ---- O += P * V (3-pass split) ----
        #pragma unroll
        for (int g = 0; g < 4; g++) {
            uint32_t ah[4], al[4];
            packhl(S[2*g][0],   S[2*g][1],   ah[0], al[0]);
            packhl(S[2*g][2],   S[2*g][3],   ah[1], al[1]);
            packhl(S[2*g+1][0], S[2*g+1][1], ah[2], al[2]);
            packhl(S[2*g+1][2], S[2*g+1][3], ah[3], al[3]);
            #pragma unroll
            for (int ntp = 0; ntp < 4; ntp++) {
                uint32_t vaddr = stgb + 18432u
                    + (uint32_t)(((g * 16 + (lane & 15)) * QS
                                  + ntp * 16 + ((lane >> 4) << 3)) * 2);
                uint32_t vh[4], vl[4];
                ldm_x4t(vh, vaddr);            // VH at stage offset 18432 B
                ldm_x4t(vl, vaddr + 9216u);    // VL at 27648 B
                mma_bf16(O[2*ntp],   ah, vh);
                mma_bf16(O[2*ntp],   ah, vl);
                mma_bf16(O[2*ntp],   al, vh);
                mma_bf16(O[2*ntp+1], ah, vh + 2);
                mma_bf16(O[2*ntp+1], ah, vl + 2);
                mma_bf16(O[2*ntp+1], al, vh + 2);
            }
        }
    }

    // Finalize: pack to bf16 hi/lo and store y
    float il0 = 1.f / l0, il1 = 1.f / l1;
    int rowg = qt * 128 + r0 + (lane >> 2);
    #pragma unroll
    for (int nt = 0; nt < 8; nt++) {
        int hd = nt * 8 + (lane & 3) * 2;
        size_t o0 = (size_t)(b * Ln + rowg) * Dn + h * 64 + hd;
        size_t o1 = (size_t)(b * Ln + rowg + 8) * Dn + h * 64 + hd;
        uint32_t hw, lw;
        packhl(O[nt][0] * il0, O[nt][1] * il0, hw, lw);
        *(uint32_t*)(g_yh + o0) = hw;
        *(uint32_t*)(g_yl + o0) = lw;
        packhl(O[nt][2] * il1, O[nt][3] * il1, hw, lw);
        *(uint32_t*)(g_yh + o1) = hw;
        *(uint32_t*)(g_yl + o1) = lw;
    }
}

// ---------------------------------------------------------------------------
extern "C" void kernel_launch(void* const* d_in, const int* in_sizes, int n_in,
                              void* d_out, int out_size)
{
    (void)in_sizes; (void)n_in; (void)out_size;
    const float* x  = (const float*)d_in[0];
    const float* Wq = (const float*)d_in[1];
    const float* Wk = (const float*)d_in[2];
    const float* Wv = (const float*)d_in[3];
    const float* Wo = (const float*)d_in[4];
    float* out = (float*)d_out;

    cudaFuncSetAttribute(gemm_mma_kernel,
                         cudaFuncAttributeMaxDynamicSharedMemorySize,
                         GEMM_SMEM_BYTES);
    cudaFuncSetAttribute(attn_kernel,
                         cudaFuncAttributeMaxDynamicSharedMemorySize,
                         ATTN_SMEM_BYTES);

    split_kernel<<<8192, 256>>>(x, Wq, Wk, Wv, Wo);
    gemm_mma_kernel<<<dim3(Dn/64, NROW/128, 3), 256, GEMM_SMEM_BYTES>>>(nullptr, 0);
    attn_kernel<<<dim3(Ln/128, Hn, Bn), 256, ATTN_SMEM_BYTES>>>();
    gemm_mma_kernel<<<dim3(Dn/64, NROW/128, 1), 256, GEMM_SMEM_BYTES>>>(out, 1);
}